// round 1
// baseline (speedup 1.0000x reference)
#include <cuda_runtime.h>
#include <cuda_bf16.h>
#include <math_constants.h>

// Problem dims (fixed by the dataset)
#define TOK   2048      // B*S = 2*1024
#define DMODEL 2048
#define HID   5632
#define NEXP  8
#define RANK  16
#define KTOP  2
#define SEQ   1024
#define ALPHA 2.0f

// ---------------- scratch (static __device__ — no allocation allowed) -------
__device__ __align__(256) float g_base_up[TOK * HID];
__device__ __align__(256) float g_base_gate[TOK * HID];
__device__ __align__(256) float g_mixed[TOK * HID];
__device__ __align__(256) float g_topv[TOK * KTOP];
__device__ __align__(256) int   g_topi[TOK * KTOP];
__device__ __align__(256) float g_wf[TOK * KTOP];
__device__ __align__(256) float g_xa_up[TOK * KTOP * RANK];
__device__ __align__(256) float g_xa_gate[TOK * KTOP * RANK];
__device__ __align__(256) float g_v[TOK * KTOP * RANK];

// ---------------- packed fp32x2 helpers -------------------------------------
__device__ __forceinline__ unsigned long long pk2(float lo, float hi) {
    unsigned long long r;
    asm("mov.b64 %0, {%1, %2};" : "=l"(r) : "f"(lo), "f"(hi));
    return r;
}
__device__ __forceinline__ void fma2(unsigned long long &acc, unsigned long long a,
                                     unsigned long long b) {
    asm("fma.rn.f32x2 %0, %1, %2, %0;" : "+l"(acc) : "l"(a), "l"(b));
}
__device__ __forceinline__ void upk2(unsigned long long v, float &lo, float &hi) {
    asm("mov.b64 {%0, %1}, %2;" : "=f"(lo), "=f"(hi) : "l"(v));
}

// ---------------- K1: router logits + top-2 ---------------------------------
__global__ void router_kernel(const float* __restrict__ x,
                              const float* __restrict__ gw,
                              float* __restrict__ topv, int* __restrict__ topi) {
    int warp = threadIdx.x >> 5, lane = threadIdx.x & 31;
    int t = blockIdx.x * 8 + warp;
    const float* xr = x + (size_t)t * DMODEL;
    float p[NEXP];
#pragma unroll
    for (int e = 0; e < NEXP; e++) p[e] = 0.f;
    for (int d = lane; d < DMODEL; d += 32) {
        float xv = xr[d];
#pragma unroll
        for (int e = 0; e < NEXP; e++) p[e] = fmaf(xv, gw[e * DMODEL + d], p[e]);
    }
#pragma unroll
    for (int e = 0; e < NEXP; e++)
#pragma unroll
        for (int o = 16; o > 0; o >>= 1) p[e] += __shfl_xor_sync(~0u, p[e], o);
    if (lane == 0) {
        int i0 = 0; float v0 = p[0];
#pragma unroll
        for (int e = 1; e < NEXP; e++) if (p[e] > v0) { v0 = p[e]; i0 = e; }
        int i1 = -1; float v1 = -CUDART_INF_F;
#pragma unroll
        for (int e = 0; e < NEXP; e++) if (e != i0 && p[e] > v1) { v1 = p[e]; i1 = e; }
        topv[t * 2 + 0] = v0; topv[t * 2 + 1] = v1;
        topi[t * 2 + 0] = i0; topi[t * 2 + 1] = i1;
    }
}

// ---------------- K2: softmax over the SEQUENCE axis per (batch, slot) ------
__global__ void seq_softmax_kernel(const float* __restrict__ topv,
                                   float* __restrict__ wf) {
    int b = blockIdx.x >> 1, j = blockIdx.x & 1;
    int s = threadIdx.x;            // 1024 threads
    int lane = s & 31, warp = s >> 5;
    __shared__ float red[32];
    __shared__ float bc;
    float v = topv[(size_t)(b * SEQ + s) * 2 + j];
    float m = v;
#pragma unroll
    for (int o = 16; o > 0; o >>= 1) m = fmaxf(m, __shfl_xor_sync(~0u, m, o));
    if (lane == 0) red[warp] = m;
    __syncthreads();
    if (s < 32) {
        float mm = red[s];
#pragma unroll
        for (int o = 16; o > 0; o >>= 1) mm = fmaxf(mm, __shfl_xor_sync(~0u, mm, o));
        if (s == 0) bc = mm;
    }
    __syncthreads();
    float M = bc;
    float ev = __expf(v - M);
    float su = ev;
#pragma unroll
    for (int o = 16; o > 0; o >>= 1) su += __shfl_xor_sync(~0u, su, o);
    __syncthreads();   // red reuse
    if (lane == 0) red[warp] = su;
    __syncthreads();
    if (s < 32) {
        float ss = red[s];
#pragma unroll
        for (int o = 16; o > 0; o >>= 1) ss += __shfl_xor_sync(~0u, ss, o);
        if (s == 0) bc = ss;
    }
    __syncthreads();
    wf[(size_t)(b * SEQ + s) * 2 + j] = ev / bc;
}

// ---------------- K3: per-token x @ A^T for the 2 selected experts ----------
__global__ void lora_xa_kernel(const float* __restrict__ x,
                               const float* __restrict__ upA,
                               const float* __restrict__ gateA,
                               const int* __restrict__ topi,
                               float* __restrict__ xaU, float* __restrict__ xaG) {
    int t = blockIdx.x;
    __shared__ float xs[DMODEL];
    __shared__ int es[2];
    int tid = threadIdx.x;
    const float4* xr4 = (const float4*)(x + (size_t)t * DMODEL);
    float4* xs4 = (float4*)xs;
#pragma unroll
    for (int i = tid; i < DMODEL / 4; i += 256) xs4[i] = xr4[i];
    if (tid < 2) es[tid] = topi[t * 2 + tid];
    __syncthreads();
    int warp = tid >> 5, lane = tid & 31;
    for (int jj = warp; jj < 64; jj += 8) {
        int j = jj >> 5;            // slot 0/1
        int which = (jj >> 4) & 1;  // 0 = up, 1 = gate
        int r = jj & 15;
        const float* Ar = (which ? gateA : upA) + ((size_t)es[j] * RANK + r) * DMODEL;
        float sacc = 0.f;
        for (int d = lane; d < DMODEL; d += 32) sacc = fmaf(xs[d], Ar[d], sacc);
#pragma unroll
        for (int o = 16; o > 0; o >>= 1) sacc += __shfl_xor_sync(~0u, sacc, o);
        if (lane == 0) (which ? xaG : xaU)[t * 2 * RANK + j * RANK + r] = sacc;
    }
}

// ---------------- SGEMM-NT: C[M,N] (+)= A[M,K] * B[N,K]^T  (f32x2 core) -----
#define BM 128
#define BN 128
#define BKK 16
#define LDS_A (BM + 4)

template <bool ADD_C>
__global__ __launch_bounds__(256, 2)
void sgemm_nt(const float* __restrict__ A, const float* __restrict__ B,
              float* __restrict__ C, int M, int N, int K) {
    __shared__ float As[BKK][LDS_A];
    __shared__ float Bs[BKK][LDS_A];
    int tid = threadIdx.x;
    int bm = blockIdx.y * BM, bn = blockIdx.x * BN;
    int tx = tid & 15, ty = tid >> 4;
    int rm = ty * 8, rn = tx * 8;
    int lrow = tid >> 2;
    int lk = (tid & 3) << 2;

    const float* Ab = A + (size_t)bm * K;
    const float* Bb = B + (size_t)bn * K;

    unsigned long long acc[8][4];
#pragma unroll
    for (int m = 0; m < 8; m++)
#pragma unroll
        for (int n = 0; n < 4; n++) acc[m][n] = 0ULL;

    for (int kt = 0; kt < K; kt += BKK) {
#pragma unroll
        for (int p = 0; p < 2; p++) {
            int row = lrow + p * 64;
            float4 va = *(const float4*)&Ab[(size_t)row * K + kt + lk];
            As[lk + 0][row] = va.x; As[lk + 1][row] = va.y;
            As[lk + 2][row] = va.z; As[lk + 3][row] = va.w;
            float4 vb = *(const float4*)&Bb[(size_t)row * K + kt + lk];
            Bs[lk + 0][row] = vb.x; Bs[lk + 1][row] = vb.y;
            Bs[lk + 2][row] = vb.z; Bs[lk + 3][row] = vb.w;
        }
        __syncthreads();
#pragma unroll
        for (int k = 0; k < BKK; k++) {
            float4 a0 = *(const float4*)&As[k][rm];
            float4 a1 = *(const float4*)&As[k][rm + 4];
            float4 b0 = *(const float4*)&Bs[k][rn];
            float4 b1 = *(const float4*)&Bs[k][rn + 4];
            unsigned long long bp0 = pk2(b0.x, b0.y);
            unsigned long long bp1 = pk2(b0.z, b0.w);
            unsigned long long bp2 = pk2(b1.x, b1.y);
            unsigned long long bp3 = pk2(b1.z, b1.w);
            float av[8] = {a0.x, a0.y, a0.z, a0.w, a1.x, a1.y, a1.z, a1.w};
#pragma unroll
            for (int m = 0; m < 8; m++) {
                unsigned long long aa = pk2(av[m], av[m]);
                fma2(acc[m][0], aa, bp0);
                fma2(acc[m][1], aa, bp1);
                fma2(acc[m][2], aa, bp2);
                fma2(acc[m][3], aa, bp3);
            }
        }
        __syncthreads();
    }

#pragma unroll
    for (int m = 0; m < 8; m++) {
        float* Crow = C + (size_t)(bm + rm + m) * N + bn + rn;
#pragma unroll
        for (int n2 = 0; n2 < 4; n2++) {
            float lo, hi;
            upk2(acc[m][n2], lo, hi);
            if (ADD_C) {
                float2 old = *(const float2*)&Crow[2 * n2];
                lo += old.x; hi += old.y;
            }
            float2 st; st.x = lo; st.y = hi;
            *(float2*)&Crow[2 * n2] = st;
        }
    }
}

// ---------------- K5: fused SiLU-gate hidden + down-LoRA reduction ----------
__global__ void fused_hidden_kernel(const float* __restrict__ upB,
                                    const float* __restrict__ gateB,
                                    const float* __restrict__ downA) {
    int t = blockIdx.x;
    int tid = threadIdx.x;
    int lane = tid & 31, warp = tid >> 5;
    __shared__ __align__(16) float sxu[2][16];
    __shared__ __align__(16) float sxg[2][16];
    __shared__ float sw[2];
    __shared__ int se[2];
    __shared__ float warpsum[8][32];

    if (tid < 32) {
        int j = tid >> 4, r = tid & 15;
        sxu[j][r] = g_xa_up[t * 32 + tid];
        sxg[j][r] = g_xa_gate[t * 32 + tid];
    }
    if (tid < 2) { sw[tid] = g_wf[t * 2 + tid]; se[tid] = g_topi[t * 2 + tid]; }
    __syncthreads();

    float vacc[2][16];
#pragma unroll
    for (int j = 0; j < 2; j++)
#pragma unroll
        for (int r = 0; r < 16; r++) vacc[j][r] = 0.f;

    int e0 = se[0], e1 = se[1];
    float w0 = sw[0], w1 = sw[1];

    for (int h = tid; h < HID; h += 256) {
        float bu = g_base_up[(size_t)t * HID + h];
        float bg = g_base_gate[(size_t)t * HID + h];
        float mix = 0.f;
#pragma unroll
        for (int j = 0; j < 2; j++) {
            int e = j ? e1 : e0;
            float w = j ? w1 : w0;
            const float4* ub = (const float4*)&upB[((size_t)e * HID + h) * RANK];
            const float4* gb = (const float4*)&gateB[((size_t)e * HID + h) * RANK];
            const float4* xu = (const float4*)sxu[j];
            const float4* xg = (const float4*)sxg[j];
            float lu = 0.f, lg = 0.f;
#pragma unroll
            for (int q = 0; q < 4; q++) {
                float4 u4 = ub[q], g4 = gb[q];
                float4 a4 = xu[q], c4 = xg[q];
                lu = fmaf(a4.x, u4.x, lu); lu = fmaf(a4.y, u4.y, lu);
                lu = fmaf(a4.z, u4.z, lu); lu = fmaf(a4.w, u4.w, lu);
                lg = fmaf(c4.x, g4.x, lg); lg = fmaf(c4.y, g4.y, lg);
                lg = fmaf(c4.z, g4.z, lg); lg = fmaf(c4.w, g4.w, lg);
            }
            float uu = bu + ALPHA * lu;
            float gg = bg + ALPHA * lg;
            float hv = uu / (1.f + __expf(-uu)) * gg;   // silu(uu) * gg
            float ch = w * hv;
            mix += ch;
            const float* da = &downA[((size_t)e * RANK) * HID + h];
#pragma unroll
            for (int r = 0; r < 16; r++)
                vacc[j][r] = fmaf(ch, da[(size_t)r * HID], vacc[j][r]);
        }
        g_mixed[(size_t)t * HID + h] = mix;
    }

#pragma unroll
    for (int j = 0; j < 2; j++)
#pragma unroll
        for (int r = 0; r < 16; r++) {
            float s = vacc[j][r];
#pragma unroll
            for (int o = 16; o > 0; o >>= 1) s += __shfl_xor_sync(~0u, s, o);
            if (lane == 0) warpsum[warp][j * 16 + r] = s;
        }
    __syncthreads();
    if (tid < 32) {
        float s = 0.f;
#pragma unroll
        for (int w = 0; w < 8; w++) s += warpsum[w][tid];
        g_v[t * 32 + tid] = s;
    }
}

// ---------------- K5b: expand down-LoRA to [T, D] (writes d_out) ------------
__global__ void lora_down_kernel(const float* __restrict__ downB,
                                 float* __restrict__ out) {
    int t = blockIdx.x;
    int tid = threadIdx.x;
    __shared__ __align__(16) float sv[2][16];
    __shared__ int se[2];
    if (tid < 32) sv[tid >> 4][tid & 15] = g_v[t * 32 + tid];
    if (tid < 2) se[tid] = g_topi[t * 2 + tid];
    __syncthreads();
    int e0 = se[0], e1 = se[1];
    for (int d = tid; d < DMODEL; d += 256) {
        float acc = 0.f;
#pragma unroll
        for (int j = 0; j < 2; j++) {
            int e = j ? e1 : e0;
            const float4* db = (const float4*)&downB[((size_t)e * DMODEL + d) * RANK];
            const float4* vv = (const float4*)sv[j];
#pragma unroll
            for (int q = 0; q < 4; q++) {
                float4 b4 = db[q], v4 = vv[q];
                acc = fmaf(v4.x, b4.x, acc); acc = fmaf(v4.y, b4.y, acc);
                acc = fmaf(v4.z, b4.z, acc); acc = fmaf(v4.w, b4.w, acc);
            }
        }
        out[(size_t)t * DMODEL + d] = ALPHA * acc;
    }
}

// ---------------- launch --------------------------------------------------
extern "C" void kernel_launch(void* const* d_in, const int* in_sizes, int n_in,
                              void* d_out, int out_size) {
    const float* x      = (const float*)d_in[0];
    const float* gate_w = (const float*)d_in[1];
    const float* w_up   = (const float*)d_in[2];
    const float* w_gate = (const float*)d_in[3];
    const float* w_down = (const float*)d_in[4];
    const float* up_A   = (const float*)d_in[5];
    const float* up_B   = (const float*)d_in[6];
    const float* gate_A = (const float*)d_in[7];
    const float* gate_B = (const float*)d_in[8];
    const float* down_A = (const float*)d_in[9];
    const float* down_B = (const float*)d_in[10];
    float* out = (float*)d_out;

    static float *p_base_up = nullptr, *p_base_gate = nullptr, *p_mixed = nullptr,
                 *p_topv = nullptr, *p_wf = nullptr, *p_xau = nullptr, *p_xag = nullptr;
    static int* p_topi = nullptr;
    if (!p_base_up) {
        cudaGetSymbolAddress((void**)&p_base_up, g_base_up);
        cudaGetSymbolAddress((void**)&p_base_gate, g_base_gate);
        cudaGetSymbolAddress((void**)&p_mixed, g_mixed);
        cudaGetSymbolAddress((void**)&p_topv, g_topv);
        cudaGetSymbolAddress((void**)&p_topi, g_topi);
        cudaGetSymbolAddress((void**)&p_wf, g_wf);
        cudaGetSymbolAddress((void**)&p_xau, g_xa_up);
        cudaGetSymbolAddress((void**)&p_xag, g_xa_gate);
    }

    // K1: router logits + top-2
    router_kernel<<<TOK / 8, 256>>>(x, gate_w, p_topv, p_topi);
    // K2: softmax over sequence axis
    seq_softmax_kernel<<<4, SEQ>>>(p_topv, p_wf);
    // K3: per-token LoRA-A projections (selected experts only)
    lora_xa_kernel<<<TOK, 256>>>(x, up_A, gate_A, p_topi, p_xau, p_xag);
    // K4: base up/gate projections (big GEMMs)
    {
        dim3 grid(HID / BN, TOK / BM);
        sgemm_nt<false><<<grid, 256>>>(x, w_up, p_base_up, TOK, HID, DMODEL);
        sgemm_nt<false><<<grid, 256>>>(x, w_gate, p_base_gate, TOK, HID, DMODEL);
    }
    // K5: fused SiLU-gate hidden, routed mix, down-LoRA rank reduction
    fused_hidden_kernel<<<TOK, 256>>>(up_B, gate_B, down_A);
    // K5b: lora_down -> d_out
    lora_down_kernel<<<TOK, 256>>>(down_B, out);
    // K6: out += mixed @ w_down^T
    {
        dim3 grid(DMODEL / BN, TOK / BM);
        sgemm_nt<true><<<grid, 256>>>(p_mixed, w_down, out, TOK, DMODEL, HID);
    }
}

// round 4
// speedup vs baseline: 1.6009x; 1.6009x over previous
#include <cuda_runtime.h>
#include <cuda_bf16.h>
#include <math_constants.h>
#include <cstdint>

// Problem dims (fixed by the dataset)
#define TOK    2048      // B*S = 2*1024
#define DMODEL 2048
#define HID    5632
#define NEXP   8
#define RANK   16
#define SEQ    1024
#define ALPHA  2.0f

#define K3_UP  (3*DMODEL)   // 6144
#define K3_DN  (3*HID)      // 16896

// ---------------- scratch (static __device__ — no allocation allowed) -------
__device__ __align__(256) float g_base_up[TOK * HID];
__device__ __align__(256) float g_base_gate[TOK * HID];
__device__ __align__(256) float g_mixed[TOK * HID];
__device__ __align__(256) float g_topv[TOK * 2];
__device__ __align__(256) int   g_topi[TOK * 2];
__device__ __align__(256) float g_wf[TOK * 2];
__device__ __align__(256) float g_xa_up[TOK * 2 * RANK];
__device__ __align__(256) float g_xa_gate[TOK * 2 * RANK];
__device__ __align__(256) float g_v[TOK * 2 * RANK];

// bf16x3 split operands
__device__ __align__(256) __nv_bfloat16 g_x3[(size_t)TOK * K3_UP];
__device__ __align__(256) __nv_bfloat16 g_wup3[(size_t)HID * K3_UP];
__device__ __align__(256) __nv_bfloat16 g_wgate3[(size_t)HID * K3_UP];
__device__ __align__(256) __nv_bfloat16 g_wdown3[(size_t)DMODEL * K3_DN];
__device__ __align__(256) __nv_bfloat16 g_mixed3[(size_t)TOK * K3_DN];

// ---------------- helpers ----------------------------------------------------
__device__ __forceinline__ uint32_t smem_u32(const void* p) {
    uint32_t a;
    asm("{ .reg .u64 t; cvta.to.shared.u64 t, %1; cvt.u32.u64 %0, t; }"
        : "=r"(a) : "l"(p));
    return a;
}
__device__ __forceinline__ void cp16(uint32_t saddr, const void* gaddr) {
    asm volatile("cp.async.cg.shared.global [%0], [%1], 16;"
                 :: "r"(saddr), "l"(gaddr) : "memory");
}
__device__ __forceinline__ void cp_commit() {
    asm volatile("cp.async.commit_group;" ::: "memory");
}
template <int N>
__device__ __forceinline__ void cp_wait() {
    asm volatile("cp.async.wait_group %0;" :: "n"(N) : "memory");
}
__device__ __forceinline__ void ldsm_x4(uint32_t& r0, uint32_t& r1, uint32_t& r2,
                                        uint32_t& r3, uint32_t addr) {
    asm volatile("ldmatrix.sync.aligned.m8n8.x4.shared.b16 {%0,%1,%2,%3}, [%4];"
                 : "=r"(r0), "=r"(r1), "=r"(r2), "=r"(r3) : "r"(addr));
}
__device__ __forceinline__ void mma_bf16(float* c, const uint32_t* a, const uint32_t* b) {
    asm volatile(
        "mma.sync.aligned.m16n8k16.row.col.f32.bf16.bf16.f32 "
        "{%0,%1,%2,%3}, {%4,%5,%6,%7}, {%8,%9}, {%0,%1,%2,%3};"
        : "+f"(c[0]), "+f"(c[1]), "+f"(c[2]), "+f"(c[3])
        : "r"(a[0]), "r"(a[1]), "r"(a[2]), "r"(a[3]), "r"(b[0]), "r"(b[1]));
}

// ---------------- K1: router logits + top-2 ---------------------------------
__global__ void router_kernel(const float* __restrict__ x,
                              const float* __restrict__ gw,
                              float* __restrict__ topv, int* __restrict__ topi) {
    int warp = threadIdx.x >> 5, lane = threadIdx.x & 31;
    int t = blockIdx.x * 8 + warp;
    const float* xr = x + (size_t)t * DMODEL;
    float p[NEXP];
#pragma unroll
    for (int e = 0; e < NEXP; e++) p[e] = 0.f;
    for (int d = lane; d < DMODEL; d += 32) {
        float xv = xr[d];
#pragma unroll
        for (int e = 0; e < NEXP; e++) p[e] = fmaf(xv, gw[e * DMODEL + d], p[e]);
    }
#pragma unroll
    for (int e = 0; e < NEXP; e++)
#pragma unroll
        for (int o = 16; o > 0; o >>= 1) p[e] += __shfl_xor_sync(~0u, p[e], o);
    if (lane == 0) {
        int i0 = 0; float v0 = p[0];
#pragma unroll
        for (int e = 1; e < NEXP; e++) if (p[e] > v0) { v0 = p[e]; i0 = e; }
        int i1 = -1; float v1 = -CUDART_INF_F;
#pragma unroll
        for (int e = 0; e < NEXP; e++) if (e != i0 && p[e] > v1) { v1 = p[e]; i1 = e; }
        topv[t * 2 + 0] = v0; topv[t * 2 + 1] = v1;
        topi[t * 2 + 0] = i0; topi[t * 2 + 1] = i1;
    }
}

// ---------------- K2: softmax over the SEQUENCE axis per (batch, slot) ------
__global__ void seq_softmax_kernel(const float* __restrict__ topv,
                                   float* __restrict__ wf) {
    int b = blockIdx.x >> 1, j = blockIdx.x & 1;
    int s = threadIdx.x;
    int lane = s & 31, warp = s >> 5;
    __shared__ float red[32];
    __shared__ float bc;
    float v = topv[(size_t)(b * SEQ + s) * 2 + j];
    float m = v;
#pragma unroll
    for (int o = 16; o > 0; o >>= 1) m = fmaxf(m, __shfl_xor_sync(~0u, m, o));
    if (lane == 0) red[warp] = m;
    __syncthreads();
    if (s < 32) {
        float mm = red[s];
#pragma unroll
        for (int o = 16; o > 0; o >>= 1) mm = fmaxf(mm, __shfl_xor_sync(~0u, mm, o));
        if (s == 0) bc = mm;
    }
    __syncthreads();
    float M = bc;
    float ev = __expf(v - M);
    float su = ev;
#pragma unroll
    for (int o = 16; o > 0; o >>= 1) su += __shfl_xor_sync(~0u, su, o);
    __syncthreads();
    if (lane == 0) red[warp] = su;
    __syncthreads();
    if (s < 32) {
        float ss = red[s];
#pragma unroll
        for (int o = 16; o > 0; o >>= 1) ss += __shfl_xor_sync(~0u, ss, o);
        if (s == 0) bc = ss;
    }
    __syncthreads();
    wf[(size_t)(b * SEQ + s) * 2 + j] = ev / bc;
}

// ---------------- K3: per-token x @ A^T for the 2 selected experts ----------
__global__ void lora_xa_kernel(const float* __restrict__ x,
                               const float* __restrict__ upA,
                               const float* __restrict__ gateA,
                               const int* __restrict__ topi,
                               float* __restrict__ xaU, float* __restrict__ xaG) {
    int t = blockIdx.x;
    __shared__ float xs[DMODEL];
    __shared__ int es[2];
    int tid = threadIdx.x;
    const float4* xr4 = (const float4*)(x + (size_t)t * DMODEL);
    float4* xs4 = (float4*)xs;
#pragma unroll
    for (int i = tid; i < DMODEL / 4; i += 256) xs4[i] = xr4[i];
    if (tid < 2) es[tid] = topi[t * 2 + tid];
    __syncthreads();
    int warp = tid >> 5, lane = tid & 31;
    for (int jj = warp; jj < 64; jj += 8) {
        int j = jj >> 5;
        int which = (jj >> 4) & 1;
        int r = jj & 15;
        const float* Ar = (which ? gateA : upA) + ((size_t)es[j] * RANK + r) * DMODEL;
        float sacc = 0.f;
        for (int d = lane; d < DMODEL; d += 32) sacc = fmaf(xs[d], Ar[d], sacc);
#pragma unroll
        for (int o = 16; o > 0; o >>= 1) sacc += __shfl_xor_sync(~0u, sacc, o);
        if (lane == 0) (which ? xaG : xaU)[t * 2 * RANK + j * RANK + r] = sacc;
    }
}

// ---------------- K4a: fp32 -> bf16 hi/lo K-extended split ------------------
// A-operand layout [hi | lo | hi]: loOff=K, hi2Off=2K
// B-operand layout [hi | hi | lo]: hi2Off=K, loOff=2K
__global__ void cvt3_kernel(const float* __restrict__ src,
                            __nv_bfloat16* __restrict__ dst,
                            long long n, int K, long long loOff, long long hi2Off) {
    long long i = ((long long)blockIdx.x * blockDim.x + threadIdx.x) * 2;
    if (i >= n) return;
    float2 v = *(const float2*)(src + i);
    long long row = i / K;
    long long k = i - row * K;
    __nv_bfloat16 hx = __float2bfloat16(v.x);
    __nv_bfloat16 hy = __float2bfloat16(v.y);
    __nv_bfloat16 lx = __float2bfloat16(v.x - __bfloat162float(hx));
    __nv_bfloat16 ly = __float2bfloat16(v.y - __bfloat162float(hy));
    __nv_bfloat162 hv; hv.x = hx; hv.y = hy;
    __nv_bfloat162 lv; lv.x = lx; lv.y = ly;
    __nv_bfloat16* base = dst + row * (3LL * K) + k;
    *(__nv_bfloat162*)(base) = hv;
    *(__nv_bfloat162*)(base + loOff) = lv;
    *(__nv_bfloat162*)(base + hi2Off) = hv;
}

// ---------------- K4b: HMMA bf16 GEMM  C[M,N] (+)= A[M,K3] B[N,K3]^T --------
// CTA 128x128, K-chunk 32, 2-stage cp.async pipeline, 8 warps (warp tile 32x64).
#define TM 128
#define TN 128
#define TKC 32
#define ASTR 40           // row stride in bf16 elements (32 data + 8 pad)

template <bool ADD_C>
__global__ __launch_bounds__(256)
void gemm_mma(const __nv_bfloat16* __restrict__ A,
              const __nv_bfloat16* __restrict__ B,
              float* __restrict__ C, int N, int K3) {
    __shared__ __nv_bfloat16 sA[2][TM * ASTR];
    __shared__ __nv_bfloat16 sB[2][TN * ASTR];

    int tid = threadIdx.x;
    int wid = tid >> 5, lane = tid & 31;
    int wm = (wid >> 1) * 32;      // warp m offset
    int wn = (wid & 1) * 64;       // warp n offset

    int bm = blockIdx.y * TM;
    int bn = blockIdx.x * TN;
    const __nv_bfloat16* Ag = A + (size_t)bm * K3;
    const __nv_bfloat16* Bg = B + (size_t)bn * K3;
    int niter = K3 / TKC;

    int lrow = tid >> 2;           // 0..63? no: 256 threads -> tid>>2 in 0..63
    int lseg = tid & 3;

    uint32_t sA_base[2], sB_base[2];
#pragma unroll
    for (int s = 0; s < 2; s++) {
        sA_base[s] = smem_u32(sA[s]);
        sB_base[s] = smem_u32(sB[s]);
    }

    // stage loader: 128 rows x 4 segs per operand; 256 threads -> 2 rows each
    auto load_stage = [&](int it) {
        int s = it & 1;
        int k0 = it * TKC;
#pragma unroll
        for (int h = 0; h < 2; h++) {
            int r = lrow + h * 64;
            uint32_t soff = (uint32_t)(r * ASTR + lseg * 8) * 2u;
            cp16(sA_base[s] + soff, Ag + (size_t)r * K3 + k0 + lseg * 8);
            cp16(sB_base[s] + soff, Bg + (size_t)r * K3 + k0 + lseg * 8);
        }
        cp_commit();
    };

    float acc[2][8][4];
#pragma unroll
    for (int mt = 0; mt < 2; mt++)
#pragma unroll
        for (int nt = 0; nt < 8; nt++)
#pragma unroll
            for (int q = 0; q < 4; q++) acc[mt][nt][q] = 0.f;

    load_stage(0);

    int lm = lane & 15;            // ldmatrix row-within-16
    int lk = (lane >> 4) * 8;      // ldmatrix k-half select

    for (int it = 0; it < niter; it++) {
        if (it + 1 < niter) { load_stage(it + 1); cp_wait<1>(); }
        else cp_wait<0>();
        __syncthreads();

        int s = it & 1;
#pragma unroll
        for (int kk = 0; kk < 2; kk++) {        // two k16 halves of the chunk
            uint32_t a[2][4];
#pragma unroll
            for (int mt = 0; mt < 2; mt++) {
                uint32_t addr = sA_base[s] +
                    (uint32_t)((wm + mt * 16 + lm) * ASTR + kk * 16 + lk) * 2u;
                ldsm_x4(a[mt][0], a[mt][1], a[mt][2], a[mt][3], addr);
            }
            uint32_t b[8][2];
#pragma unroll
            for (int np = 0; np < 4; np++) {    // each x4 covers two n-tiles
                uint32_t r0, r1, r2, r3;
                uint32_t addr = sB_base[s] +
                    (uint32_t)((wn + np * 16 + lm) * ASTR + kk * 16 + lk) * 2u;
                ldsm_x4(r0, r1, r2, r3, addr);
                b[np * 2 + 0][0] = r0; b[np * 2 + 0][1] = r2;
                b[np * 2 + 1][0] = r1; b[np * 2 + 1][1] = r3;
            }
#pragma unroll
            for (int mt = 0; mt < 2; mt++)
#pragma unroll
                for (int nt = 0; nt < 8; nt++)
                    mma_bf16(acc[mt][nt], a[mt], b[nt]);
        }
        __syncthreads();
    }

    // epilogue: c0,c1 -> (row, col..col+1); c2,c3 -> (row+8, ...)
    int rbase = bm + wm + (lane >> 2);
    int cbase = bn + wn + (lane & 3) * 2;
#pragma unroll
    for (int mt = 0; mt < 2; mt++) {
#pragma unroll
        for (int nt = 0; nt < 8; nt++) {
            float* p0 = C + (size_t)(rbase + mt * 16) * N + cbase + nt * 8;
            float* p1 = p0 + (size_t)8 * N;
            float2 v0 = make_float2(acc[mt][nt][0], acc[mt][nt][1]);
            float2 v1 = make_float2(acc[mt][nt][2], acc[mt][nt][3]);
            if (ADD_C) {
                float2 o0 = *(const float2*)p0;
                float2 o1 = *(const float2*)p1;
                v0.x += o0.x; v0.y += o0.y;
                v1.x += o1.x; v1.y += o1.y;
            }
            *(float2*)p0 = v0;
            *(float2*)p1 = v1;
        }
    }
}

// ---------------- K5: fused SiLU-gate hidden + down-LoRA reduction ----------
__global__ void fused_hidden_kernel(const float* __restrict__ upB,
                                    const float* __restrict__ gateB,
                                    const float* __restrict__ downA) {
    int t = blockIdx.x;
    int tid = threadIdx.x;
    int lane = tid & 31, warp = tid >> 5;
    __shared__ __align__(16) float sxu[2][16];
    __shared__ __align__(16) float sxg[2][16];
    __shared__ float sw[2];
    __shared__ int se[2];
    __shared__ float warpsum[8][32];

    if (tid < 32) {
        int j = tid >> 4, r = tid & 15;
        sxu[j][r] = g_xa_up[t * 32 + tid];
        sxg[j][r] = g_xa_gate[t * 32 + tid];
    }
    if (tid < 2) { sw[tid] = g_wf[t * 2 + tid]; se[tid] = g_topi[t * 2 + tid]; }
    __syncthreads();

    float vacc[2][16];
#pragma unroll
    for (int j = 0; j < 2; j++)
#pragma unroll
        for (int r = 0; r < 16; r++) vacc[j][r] = 0.f;

    int e0 = se[0], e1 = se[1];
    float w0 = sw[0], w1 = sw[1];

    for (int h = tid; h < HID; h += 256) {
        float bu = g_base_up[(size_t)t * HID + h];
        float bg = g_base_gate[(size_t)t * HID + h];
        float mix = 0.f;
#pragma unroll
        for (int j = 0; j < 2; j++) {
            int e = j ? e1 : e0;
            float w = j ? w1 : w0;
            const float4* ub = (const float4*)&upB[((size_t)e * HID + h) * RANK];
            const float4* gb = (const float4*)&gateB[((size_t)e * HID + h) * RANK];
            const float4* xu = (const float4*)sxu[j];
            const float4* xg = (const float4*)sxg[j];
            float lu = 0.f, lg = 0.f;
#pragma unroll
            for (int q = 0; q < 4; q++) {
                float4 u4 = ub[q], g4 = gb[q];
                float4 a4 = xu[q], c4 = xg[q];
                lu = fmaf(a4.x, u4.x, lu); lu = fmaf(a4.y, u4.y, lu);
                lu = fmaf(a4.z, u4.z, lu); lu = fmaf(a4.w, u4.w, lu);
                lg = fmaf(c4.x, g4.x, lg); lg = fmaf(c4.y, g4.y, lg);
                lg = fmaf(c4.z, g4.z, lg); lg = fmaf(c4.w, g4.w, lg);
            }
            float uu = bu + ALPHA * lu;
            float gg = bg + ALPHA * lg;
            float hv = uu / (1.f + __expf(-uu)) * gg;
            float ch = w * hv;
            mix += ch;
            const float* da = &downA[((size_t)e * RANK) * HID + h];
#pragma unroll
            for (int r = 0; r < 16; r++)
                vacc[j][r] = fmaf(ch, da[(size_t)r * HID], vacc[j][r]);
        }
        g_mixed[(size_t)t * HID + h] = mix;
    }

#pragma unroll
    for (int j = 0; j < 2; j++)
#pragma unroll
        for (int r = 0; r < 16; r++) {
            float s = vacc[j][r];
#pragma unroll
            for (int o = 16; o > 0; o >>= 1) s += __shfl_xor_sync(~0u, s, o);
            if (lane == 0) warpsum[warp][j * 16 + r] = s;
        }
    __syncthreads();
    if (tid < 32) {
        float s = 0.f;
#pragma unroll
        for (int w = 0; w < 8; w++) s += warpsum[w][tid];
        g_v[t * 32 + tid] = s;
    }
}

// ---------------- K6: expand down-LoRA to [T, D] (writes d_out) -------------
__global__ void lora_down_kernel(const float* __restrict__ downB,
                                 float* __restrict__ out) {
    int t = blockIdx.x;
    int tid = threadIdx.x;
    __shared__ __align__(16) float sv[2][16];
    __shared__ int se[2];
    if (tid < 32) sv[tid >> 4][tid & 15] = g_v[t * 32 + tid];
    if (tid < 2) se[tid] = g_topi[t * 2 + tid];
    __syncthreads();
    int e0 = se[0], e1 = se[1];
    for (int d = tid; d < DMODEL; d += 256) {
        float acc = 0.f;
#pragma unroll
        for (int j = 0; j < 2; j++) {
            int e = j ? e1 : e0;
            const float4* db = (const float4*)&downB[((size_t)e * DMODEL + d) * RANK];
            const float4* vv = (const float4*)sv[j];
#pragma unroll
            for (int q = 0; q < 4; q++) {
                float4 b4 = db[q], v4 = vv[q];
                acc = fmaf(v4.x, b4.x, acc); acc = fmaf(v4.y, b4.y, acc);
                acc = fmaf(v4.z, b4.z, acc); acc = fmaf(v4.w, b4.w, acc);
            }
        }
        out[(size_t)t * DMODEL + d] = ALPHA * acc;
    }
}

// ---------------- launch -----------------------------------------------------
extern "C" void kernel_launch(void* const* d_in, const int* in_sizes, int n_in,
                              void* d_out, int out_size) {
    const float* x      = (const float*)d_in[0];
    const float* gate_w = (const float*)d_in[1];
    const float* w_up   = (const float*)d_in[2];
    const float* w_gate = (const float*)d_in[3];
    const float* w_down = (const float*)d_in[4];
    const float* up_A   = (const float*)d_in[5];
    const float* up_B   = (const float*)d_in[6];
    const float* gate_A = (const float*)d_in[7];
    const float* gate_B = (const float*)d_in[8];
    const float* down_A = (const float*)d_in[9];
    const float* down_B = (const float*)d_in[10];
    float* out = (float*)d_out;

    static float *p_base_up = nullptr, *p_base_gate = nullptr, *p_mixed = nullptr,
                 *p_topv = nullptr, *p_wf = nullptr, *p_xau = nullptr, *p_xag = nullptr;
    static int* p_topi = nullptr;
    static __nv_bfloat16 *p_x3 = nullptr, *p_wup3 = nullptr, *p_wgate3 = nullptr,
                         *p_wdown3 = nullptr, *p_mixed3 = nullptr;
    static bool inited = false;
    if (!inited) {
        cudaGetSymbolAddress((void**)&p_base_up, g_base_up);
        cudaGetSymbolAddress((void**)&p_base_gate, g_base_gate);
        cudaGetSymbolAddress((void**)&p_mixed, g_mixed);
        cudaGetSymbolAddress((void**)&p_topv, g_topv);
        cudaGetSymbolAddress((void**)&p_topi, g_topi);
        cudaGetSymbolAddress((void**)&p_wf, g_wf);
        cudaGetSymbolAddress((void**)&p_xau, g_xa_up);
        cudaGetSymbolAddress((void**)&p_xag, g_xa_gate);
        cudaGetSymbolAddress((void**)&p_x3, g_x3);
        cudaGetSymbolAddress((void**)&p_wup3, g_wup3);
        cudaGetSymbolAddress((void**)&p_wgate3, g_wgate3);
        cudaGetSymbolAddress((void**)&p_wdown3, g_wdown3);
        cudaGetSymbolAddress((void**)&p_mixed3, g_mixed3);
        inited = true;
    }

    // K1-K3: routing + per-token LoRA-A projections (fp32 inputs)
    router_kernel<<<TOK / 8, 256>>>(x, gate_w, p_topv, p_topi);
    seq_softmax_kernel<<<4, SEQ>>>(p_topv, p_wf);
    lora_xa_kernel<<<TOK, 256>>>(x, up_A, gate_A, p_topi, p_xau, p_xag);

    // bf16x3 conversions: A-operands [hi|lo|hi], B-operands [hi|hi|lo]
    {
        long long n = (long long)TOK * DMODEL;
        cvt3_kernel<<<(unsigned)((n / 2 + 255) / 256), 256>>>(x, p_x3, n, DMODEL,
                                                              DMODEL, 2LL * DMODEL);
        n = (long long)HID * DMODEL;
        cvt3_kernel<<<(unsigned)((n / 2 + 255) / 256), 256>>>(w_up, p_wup3, n, DMODEL,
                                                              2LL * DMODEL, DMODEL);
        cvt3_kernel<<<(unsigned)((n / 2 + 255) / 256), 256>>>(w_gate, p_wgate3, n, DMODEL,
                                                              2LL * DMODEL, DMODEL);
        n = (long long)DMODEL * HID;
        cvt3_kernel<<<(unsigned)((n / 2 + 255) / 256), 256>>>(w_down, p_wdown3, n, HID,
                                                              2LL * HID, HID);
    }

    // base up/gate projections on HMMA tensor cores
    {
        dim3 grid(HID / TN, TOK / TM);
        gemm_mma<false><<<grid, 256>>>(p_x3, p_wup3, p_base_up, HID, K3_UP);
        gemm_mma<false><<<grid, 256>>>(p_x3, p_wgate3, p_base_gate, HID, K3_UP);
    }

    // fused SiLU-gate hidden + down-LoRA rank reduction
    fused_hidden_kernel<<<TOK, 256>>>(up_B, gate_B, down_A);

    // convert mixed hidden for the down GEMM
    {
        long long n = (long long)TOK * HID;
        cvt3_kernel<<<(unsigned)((n / 2 + 255) / 256), 256>>>(p_mixed, p_mixed3, n, HID,
                                                              HID, 2LL * HID);
    }

    // lora_down -> out, then out += mixed @ w_down^T on HMMA
    lora_down_kernel<<<TOK, 256>>>(down_B, out);
    {
        dim3 grid(DMODEL / TN, TOK / TM);
        gemm_mma<true><<<grid, 256>>>(p_mixed3, p_wdown3, out, DMODEL, K3_DN);
    }
}

// round 6
// speedup vs baseline: 1.6728x; 1.0449x over previous
#include <cuda_runtime.h>
#include <cuda_bf16.h>
#include <math_constants.h>
#include <cstdint>

// Problem dims (fixed by the dataset)
#define TOK    2048      // B*S = 2*1024
#define DMODEL 2048
#define HID    5632
#define NEXP   8
#define RANK   16
#define SEQ    1024
#define ALPHA  2.0f

// ---------------- scratch (static __device__ — no allocation allowed) -------
__device__ __align__(256) float g_base_up[TOK * HID];
__device__ __align__(256) float g_base_gate[TOK * HID];
__device__ __align__(256) float g_topv[TOK * 2];
__device__ __align__(256) int   g_topi[TOK * 2];
__device__ __align__(256) float g_wf[TOK * 2];
__device__ __align__(256) float g_xa_up[TOK * 2 * RANK];
__device__ __align__(256) float g_xa_gate[TOK * 2 * RANK];
__device__ __align__(256) float g_v[TOK * 2 * RANK];

// bf16 hi/lo split operands (separate buffers; GEMM walks phases hh, lh, hl)
__device__ __align__(256) __nv_bfloat16 g_x_hi[(size_t)TOK * DMODEL];
__device__ __align__(256) __nv_bfloat16 g_x_lo[(size_t)TOK * DMODEL];
__device__ __align__(256) __nv_bfloat16 g_wup_hi[(size_t)HID * DMODEL];
__device__ __align__(256) __nv_bfloat16 g_wup_lo[(size_t)HID * DMODEL];
__device__ __align__(256) __nv_bfloat16 g_wgate_hi[(size_t)HID * DMODEL];
__device__ __align__(256) __nv_bfloat16 g_wgate_lo[(size_t)HID * DMODEL];
__device__ __align__(256) __nv_bfloat16 g_wdown_hi[(size_t)DMODEL * HID];
__device__ __align__(256) __nv_bfloat16 g_wdown_lo[(size_t)DMODEL * HID];
__device__ __align__(256) __nv_bfloat16 g_mix_hi[(size_t)TOK * HID];
__device__ __align__(256) __nv_bfloat16 g_mix_lo[(size_t)TOK * HID];

// ---------------- helpers ----------------------------------------------------
__device__ __forceinline__ uint32_t smem_u32(const void* p) {
    uint32_t a;
    asm("{ .reg .u64 t; cvta.to.shared.u64 t, %1; cvt.u32.u64 %0, t; }"
        : "=r"(a) : "l"(p));
    return a;
}
__device__ __forceinline__ void cp16(uint32_t saddr, const void* gaddr) {
    asm volatile("cp.async.cg.shared.global [%0], [%1], 16;"
                 :: "r"(saddr), "l"(gaddr) : "memory");
}
__device__ __forceinline__ void cp_commit() {
    asm volatile("cp.async.commit_group;" ::: "memory");
}
template <int N>
__device__ __forceinline__ void cp_wait() {
    asm volatile("cp.async.wait_group %0;" :: "n"(N) : "memory");
}
__device__ __forceinline__ void ldsm_x4(uint32_t& r0, uint32_t& r1, uint32_t& r2,
                                        uint32_t& r3, uint32_t addr) {
    asm volatile("ldmatrix.sync.aligned.m8n8.x4.shared.b16 {%0,%1,%2,%3}, [%4];"
                 : "=r"(r0), "=r"(r1), "=r"(r2), "=r"(r3) : "r"(addr));
}
__device__ __forceinline__ void mma_bf16(float* c, const uint32_t* a, const uint32_t* b) {
    asm volatile(
        "mma.sync.aligned.m16n8k16.row.col.f32.bf16.bf16.f32 "
        "{%0,%1,%2,%3}, {%4,%5,%6,%7}, {%8,%9}, {%0,%1,%2,%3};"
        : "+f"(c[0]), "+f"(c[1]), "+f"(c[2]), "+f"(c[3])
        : "r"(a[0]), "r"(a[1]), "r"(a[2]), "r"(a[3]), "r"(b[0]), "r"(b[1]));
}

// ---------------- K1: router logits + top-2 ---------------------------------
__global__ void router_kernel(const float* __restrict__ x,
                              const float* __restrict__ gw,
                              float* __restrict__ topv, int* __restrict__ topi) {
    int warp = threadIdx.x >> 5, lane = threadIdx.x & 31;
    int t = blockIdx.x * 8 + warp;
    const float* xr = x + (size_t)t * DMODEL;
    float p[NEXP];
#pragma unroll
    for (int e = 0; e < NEXP; e++) p[e] = 0.f;
    for (int d = lane; d < DMODEL; d += 32) {
        float xv = xr[d];
#pragma unroll
        for (int e = 0; e < NEXP; e++) p[e] = fmaf(xv, gw[e * DMODEL + d], p[e]);
    }
#pragma unroll
    for (int e = 0; e < NEXP; e++)
#pragma unroll
        for (int o = 16; o > 0; o >>= 1) p[e] += __shfl_xor_sync(~0u, p[e], o);
    if (lane == 0) {
        int i0 = 0; float v0 = p[0];
#pragma unroll
        for (int e = 1; e < NEXP; e++) if (p[e] > v0) { v0 = p[e]; i0 = e; }
        int i1 = -1; float v1 = -CUDART_INF_F;
#pragma unroll
        for (int e = 0; e < NEXP; e++) if (e != i0 && p[e] > v1) { v1 = p[e]; i1 = e; }
        topv[t * 2 + 0] = v0; topv[t * 2 + 1] = v1;
        topi[t * 2 + 0] = i0; topi[t * 2 + 1] = i1;
    }
}

// ---------------- K2: softmax over the SEQUENCE axis per (batch, slot) ------
__global__ void seq_softmax_kernel(const float* __restrict__ topv,
                                   float* __restrict__ wf) {
    int b = blockIdx.x >> 1, j = blockIdx.x & 1;
    int s = threadIdx.x;
    int lane = s & 31, warp = s >> 5;
    __shared__ float red[32];
    __shared__ float bc;
    float v = topv[(size_t)(b * SEQ + s) * 2 + j];
    float m = v;
#pragma unroll
    for (int o = 16; o > 0; o >>= 1) m = fmaxf(m, __shfl_xor_sync(~0u, m, o));
    if (lane == 0) red[warp] = m;
    __syncthreads();
    if (s < 32) {
        float mm = red[s];
#pragma unroll
        for (int o = 16; o > 0; o >>= 1) mm = fmaxf(mm, __shfl_xor_sync(~0u, mm, o));
        if (s == 0) bc = mm;
    }
    __syncthreads();
    float M = bc;
    float ev = __expf(v - M);
    float su = ev;
#pragma unroll
    for (int o = 16; o > 0; o >>= 1) su += __shfl_xor_sync(~0u, su, o);
    __syncthreads();
    if (lane == 0) red[warp] = su;
    __syncthreads();
    if (s < 32) {
        float ss = red[s];
#pragma unroll
        for (int o = 16; o > 0; o >>= 1) ss += __shfl_xor_sync(~0u, ss, o);
        if (s == 0) bc = ss;
    }
    __syncthreads();
    wf[(size_t)(b * SEQ + s) * 2 + j] = ev / bc;
}

// ---------------- K3: per-token x @ A^T for the 2 selected experts ----------
__global__ void lora_xa_kernel(const float* __restrict__ x,
                               const float* __restrict__ upA,
                               const float* __restrict__ gateA,
                               const int* __restrict__ topi,
                               float* __restrict__ xaU, float* __restrict__ xaG) {
    int t = blockIdx.x;
    __shared__ float xs[DMODEL];
    __shared__ int es[2];
    int tid = threadIdx.x;
    const float4* xr4 = (const float4*)(x + (size_t)t * DMODEL);
    float4* xs4 = (float4*)xs;
#pragma unroll
    for (int i = tid; i < DMODEL / 4; i += 256) xs4[i] = xr4[i];
    if (tid < 2) es[tid] = topi[t * 2 + tid];
    __syncthreads();
    int warp = tid >> 5, lane = tid & 31;
    for (int jj = warp; jj < 64; jj += 8) {
        int j = jj >> 5;
        int which = (jj >> 4) & 1;
        int r = jj & 15;
        const float* Ar = (which ? gateA : upA) + ((size_t)es[j] * RANK + r) * DMODEL;
        float sacc = 0.f;
        for (int d = lane; d < DMODEL; d += 32) sacc = fmaf(xs[d], Ar[d], sacc);
#pragma unroll
        for (int o = 16; o > 0; o >>= 1) sacc += __shfl_xor_sync(~0u, sacc, o);
        if (lane == 0) (which ? xaG : xaU)[t * 2 * RANK + j * RANK + r] = sacc;
    }
}

// ---------------- K4a: fp32 -> bf16 hi/lo split (8 elems/thread, coalesced) -
__global__ void cvt2_kernel(const float* __restrict__ src,
                            __nv_bfloat16* __restrict__ hi,
                            __nv_bfloat16* __restrict__ lo, long long n8) {
    long long i = (long long)blockIdx.x * blockDim.x + threadIdx.x;
    if (i >= n8) return;
    const float4* s = (const float4*)src + i * 2;
    float4 a = s[0], b = s[1];
    float v[8] = {a.x, a.y, a.z, a.w, b.x, b.y, b.z, b.w};
    __nv_bfloat16 h[8], l[8];
#pragma unroll
    for (int q = 0; q < 8; q++) {
        h[q] = __float2bfloat16(v[q]);
        l[q] = __float2bfloat16(v[q] - __bfloat162float(h[q]));
    }
    *((uint4*)hi + i) = *(const uint4*)h;
    *((uint4*)lo + i) = *(const uint4*)l;
}

// ---------------- K4b: HMMA bf16x3 GEMM  C[M,N] (+)= A[M,K] B[N,K]^T --------
// Phase walk: 0 = Ahi*Bhi, 1 = Alo*Bhi, 2 = Ahi*Blo  (split-precision fp32~)
// CTA 128x128, K-chunk 32, 4-stage cp.async pipeline, 8 warps (32x64 each).
#define TM 128
#define TN 128
#define TKC 32
#define ASTR 40           // row stride in bf16 elements (32 data + 8 pad)
#define STAGES 4
#define STG_ELEMS (TM * ASTR)             // per-operand per-stage elems
#define GEMM_SMEM (STAGES * STG_ELEMS * 2 * 2 * 2)  // = 163840/2? computed below

template <bool ADD_C>
__global__ __launch_bounds__(256, 2)
void gemm_mma(const __nv_bfloat16* __restrict__ Ahi,
              const __nv_bfloat16* __restrict__ Alo,
              const __nv_bfloat16* __restrict__ Bhi,
              const __nv_bfloat16* __restrict__ Blo,
              float* __restrict__ C, int N, int K) {
    extern __shared__ __nv_bfloat16 smem[];
    __nv_bfloat16* sA = smem;                         // STAGES * STG_ELEMS
    __nv_bfloat16* sB = smem + STAGES * STG_ELEMS;

    int tid = threadIdx.x;
    int wid = tid >> 5, lane = tid & 31;
    int wm = (wid >> 1) * 32;
    int wn = (wid & 1) * 64;

    int bm = blockIdx.y * TM;
    int bn = blockIdx.x * TN;
    int kchunks = K / TKC;
    int niter = 3 * kchunks;

    int lrow = tid >> 2;          // 0..63
    int lseg = tid & 3;

    uint32_t sA_u = smem_u32(sA);
    uint32_t sB_u = smem_u32(sB);

    auto load_stage = [&](int it) {
        int s = it & (STAGES - 1);
        int phase = it / kchunks;
        int k0 = (it - phase * kchunks) * TKC;
        const __nv_bfloat16* Asrc = ((phase == 1) ? Alo : Ahi) + (size_t)bm * K + k0;
        const __nv_bfloat16* Bsrc = ((phase == 2) ? Blo : Bhi) + (size_t)bn * K + k0;
        uint32_t so = (uint32_t)(s * STG_ELEMS) * 2u;
#pragma unroll
        for (int h = 0; h < 2; h++) {
            int r = lrow + h * 64;
            uint32_t off = so + (uint32_t)(r * ASTR + lseg * 8) * 2u;
            cp16(sA_u + off, Asrc + (size_t)r * K + lseg * 8);
            cp16(sB_u + off, Bsrc + (size_t)r * K + lseg * 8);
        }
    };

    float acc[2][8][4];
#pragma unroll
    for (int mt = 0; mt < 2; mt++)
#pragma unroll
        for (int nt = 0; nt < 8; nt++)
#pragma unroll
            for (int q = 0; q < 4; q++) acc[mt][nt][q] = 0.f;

    // prologue: stages 0..STAGES-2
#pragma unroll
    for (int it = 0; it < STAGES - 1; it++) { load_stage(it); cp_commit(); }

    int lm = lane & 15;
    int lk = (lane >> 4) * 8;

    for (int it = 0; it < niter; it++) {
        cp_wait<STAGES - 2>();
        __syncthreads();
        // issue next load into the stage freed at it-1 (safe past the barrier)
        if (it + STAGES - 1 < niter) load_stage(it + STAGES - 1);
        cp_commit();

        int s = it & (STAGES - 1);
        uint32_t sAo = sA_u + (uint32_t)(s * STG_ELEMS) * 2u;
        uint32_t sBo = sB_u + (uint32_t)(s * STG_ELEMS) * 2u;
#pragma unroll
        for (int kk = 0; kk < 2; kk++) {
            uint32_t a[2][4];
#pragma unroll
            for (int mt = 0; mt < 2; mt++) {
                uint32_t addr = sAo +
                    (uint32_t)((wm + mt * 16 + lm) * ASTR + kk * 16 + lk) * 2u;
                ldsm_x4(a[mt][0], a[mt][1], a[mt][2], a[mt][3], addr);
            }
            uint32_t b[8][2];
#pragma unroll
            for (int np = 0; np < 4; np++) {
                uint32_t r0, r1, r2, r3;
                uint32_t addr = sBo +
                    (uint32_t)((wn + np * 16 + lm) * ASTR + kk * 16 + lk) * 2u;
                ldsm_x4(r0, r1, r2, r3, addr);
                b[np * 2 + 0][0] = r0; b[np * 2 + 0][1] = r2;
                b[np * 2 + 1][0] = r1; b[np * 2 + 1][1] = r3;
            }
#pragma unroll
            for (int mt = 0; mt < 2; mt++)
#pragma unroll
                for (int nt = 0; nt < 8; nt++)
                    mma_bf16(acc[mt][nt], a[mt], b[nt]);
        }
    }

    int rbase = bm + wm + (lane >> 2);
    int cbase = bn + wn + (lane & 3) * 2;
#pragma unroll
    for (int mt = 0; mt < 2; mt++) {
#pragma unroll
        for (int nt = 0; nt < 8; nt++) {
            float* p0 = C + (size_t)(rbase + mt * 16) * N + cbase + nt * 8;
            float* p1 = p0 + (size_t)8 * N;
            float2 v0 = make_float2(acc[mt][nt][0], acc[mt][nt][1]);
            float2 v1 = make_float2(acc[mt][nt][2], acc[mt][nt][3]);
            if (ADD_C) {
                float2 o0 = *(const float2*)p0;
                float2 o1 = *(const float2*)p1;
                v0.x += o0.x; v0.y += o0.y;
                v1.x += o1.x; v1.y += o1.y;
            }
            *(float2*)p0 = v0;
            *(float2*)p1 = v1;
        }
    }
}

// ---------------- K5: fused SiLU-gate hidden + down-LoRA reduction ----------
// Emits mixed hidden directly as bf16 hi/lo (fuses the down-GEMM A conversion).
__global__ void fused_hidden_kernel(const float* __restrict__ upB,
                                    const float* __restrict__ gateB,
                                    const float* __restrict__ downA) {
    int t = blockIdx.x;
    int tid = threadIdx.x;
    int lane = tid & 31, warp = tid >> 5;
    __shared__ __align__(16) float sxu[2][16];
    __shared__ __align__(16) float sxg[2][16];
    __shared__ float sw[2];
    __shared__ int se[2];
    __shared__ float warpsum[8][32];

    if (tid < 32) {
        int j = tid >> 4, r = tid & 15;
        sxu[j][r] = g_xa_up[t * 32 + tid];
        sxg[j][r] = g_xa_gate[t * 32 + tid];
    }
    if (tid < 2) { sw[tid] = g_wf[t * 2 + tid]; se[tid] = g_topi[t * 2 + tid]; }
    __syncthreads();

    float vacc[2][16];
#pragma unroll
    for (int j = 0; j < 2; j++)
#pragma unroll
        for (int r = 0; r < 16; r++) vacc[j][r] = 0.f;

    int e0 = se[0], e1 = se[1];
    float w0 = sw[0], w1 = sw[1];

    for (int h = tid; h < HID; h += 256) {
        float bu = g_base_up[(size_t)t * HID + h];
        float bg = g_base_gate[(size_t)t * HID + h];
        float mix = 0.f;
#pragma unroll
        for (int j = 0; j < 2; j++) {
            int e = j ? e1 : e0;
            float w = j ? w1 : w0;
            const float4* ub = (const float4*)&upB[((size_t)e * HID + h) * RANK];
            const float4* gb = (const float4*)&gateB[((size_t)e * HID + h) * RANK];
            const float4* xu = (const float4*)sxu[j];
            const float4* xg = (const float4*)sxg[j];
            float lu = 0.f, lg = 0.f;
#pragma unroll
            for (int q = 0; q < 4; q++) {
                float4 u4 = ub[q], g4 = gb[q];
                float4 a4 = xu[q], c4 = xg[q];
                lu = fmaf(a4.x, u4.x, lu); lu = fmaf(a4.y, u4.y, lu);
                lu = fmaf(a4.z, u4.z, lu); lu = fmaf(a4.w, u4.w, lu);
                lg = fmaf(c4.x, g4.x, lg); lg = fmaf(c4.y, g4.y, lg);
                lg = fmaf(c4.z, g4.z, lg); lg = fmaf(c4.w, g4.w, lg);
            }
            float uu = bu + ALPHA * lu;
            float gg = bg + ALPHA * lg;
            float hv = uu / (1.f + __expf(-uu)) * gg;
            float ch = w * hv;
            mix += ch;
            const float* da = &downA[((size_t)e * RANK) * HID + h];
#pragma unroll
            for (int r = 0; r < 16; r++)
                vacc[j][r] = fmaf(ch, da[(size_t)r * HID], vacc[j][r]);
        }
        __nv_bfloat16 mh = __float2bfloat16(mix);
        g_mix_hi[(size_t)t * HID + h] = mh;
        g_mix_lo[(size_t)t * HID + h] = __float2bfloat16(mix - __bfloat162float(mh));
    }

#pragma unroll
    for (int j = 0; j < 2; j++)
#pragma unroll
        for (int r = 0; r < 16; r++) {
            float s = vacc[j][r];
#pragma unroll
            for (int o = 16; o > 0; o >>= 1) s += __shfl_xor_sync(~0u, s, o);
            if (lane == 0) warpsum[warp][j * 16 + r] = s;
        }
    __syncthreads();
    if (tid < 32) {
        float s = 0.f;
#pragma unroll
        for (int w = 0; w < 8; w++) s += warpsum[w][tid];
        g_v[t * 32 + tid] = s;
    }
}

// ---------------- K6: expand down-LoRA to [T, D] (writes d_out) -------------
__global__ void lora_down_kernel(const float* __restrict__ downB,
                                 float* __restrict__ out) {
    int t = blockIdx.x;
    int tid = threadIdx.x;
    __shared__ __align__(16) float sv[2][16];
    __shared__ int se[2];
    if (tid < 32) sv[tid >> 4][tid & 15] = g_v[t * 32 + tid];
    if (tid < 2) se[tid] = g_topi[t * 2 + tid];
    __syncthreads();
    int e0 = se[0], e1 = se[1];
    for (int d = tid; d < DMODEL; d += 256) {
        float acc = 0.f;
#pragma unroll
        for (int j = 0; j < 2; j++) {
            int e = j ? e1 : e0;
            const float4* db = (const float4*)&downB[((size_t)e * DMODEL + d) * RANK];
            const float4* vv = (const float4*)sv[j];
#pragma unroll
            for (int q = 0; q < 4; q++) {
                float4 b4 = db[q], v4 = vv[q];
                acc = fmaf(v4.x, b4.x, acc); acc = fmaf(v4.y, b4.y, acc);
                acc = fmaf(v4.z, b4.z, acc); acc = fmaf(v4.w, b4.w, acc);
            }
        }
        out[(size_t)t * DMODEL + d] = ALPHA * acc;
    }
}

// ---------------- launch -----------------------------------------------------
#define GEMM_DSMEM (STAGES * STG_ELEMS * 2 * 2)   // A+B, bf16 -> bytes: 4*5120*2*2 = 81920

extern "C" void kernel_launch(void* const* d_in, const int* in_sizes, int n_in,
                              void* d_out, int out_size) {
    const float* x      = (const float*)d_in[0];
    const float* gate_w = (const float*)d_in[1];
    const float* w_up   = (const float*)d_in[2];
    const float* w_gate = (const float*)d_in[3];
    const float* w_down = (const float*)d_in[4];
    const float* up_A   = (const float*)d_in[5];
    const float* up_B   = (const float*)d_in[6];
    const float* gate_A = (const float*)d_in[7];
    const float* gate_B = (const float*)d_in[8];
    const float* down_A = (const float*)d_in[9];
    const float* down_B = (const float*)d_in[10];
    float* out = (float*)d_out;

    static float *p_base_up = nullptr, *p_base_gate = nullptr,
                 *p_topv = nullptr, *p_wf = nullptr, *p_xau = nullptr, *p_xag = nullptr;
    static int* p_topi = nullptr;
    static __nv_bfloat16 *p_x_hi, *p_x_lo, *p_wup_hi, *p_wup_lo,
                         *p_wgate_hi, *p_wgate_lo, *p_wdown_hi, *p_wdown_lo,
                         *p_mix_hi, *p_mix_lo;
    static bool inited = false;
    if (!inited) {
        cudaGetSymbolAddress((void**)&p_base_up, g_base_up);
        cudaGetSymbolAddress((void**)&p_base_gate, g_base_gate);
        cudaGetSymbolAddress((void**)&p_topv, g_topv);
        cudaGetSymbolAddress((void**)&p_topi, g_topi);
        cudaGetSymbolAddress((void**)&p_wf, g_wf);
        cudaGetSymbolAddress((void**)&p_xau, g_xa_up);
        cudaGetSymbolAddress((void**)&p_xag, g_xa_gate);
        cudaGetSymbolAddress((void**)&p_x_hi, g_x_hi);
        cudaGetSymbolAddress((void**)&p_x_lo, g_x_lo);
        cudaGetSymbolAddress((void**)&p_wup_hi, g_wup_hi);
        cudaGetSymbolAddress((void**)&p_wup_lo, g_wup_lo);
        cudaGetSymbolAddress((void**)&p_wgate_hi, g_wgate_hi);
        cudaGetSymbolAddress((void**)&p_wgate_lo, g_wgate_lo);
        cudaGetSymbolAddress((void**)&p_wdown_hi, g_wdown_hi);
        cudaGetSymbolAddress((void**)&p_wdown_lo, g_wdown_lo);
        cudaGetSymbolAddress((void**)&p_mix_hi, g_mix_hi);
        cudaGetSymbolAddress((void**)&p_mix_lo, g_mix_lo);
        cudaFuncSetAttribute(gemm_mma<false>,
                             cudaFuncAttributeMaxDynamicSharedMemorySize, GEMM_DSMEM);
        cudaFuncSetAttribute(gemm_mma<true>,
                             cudaFuncAttributeMaxDynamicSharedMemorySize, GEMM_DSMEM);
        inited = true;
    }

    // K1-K3: routing + per-token LoRA-A projections (fp32 inputs)
    router_kernel<<<TOK / 8, 256>>>(x, gate_w, p_topv, p_topi);
    seq_softmax_kernel<<<4, SEQ>>>(p_topv, p_wf);
    lora_xa_kernel<<<TOK, 256>>>(x, up_A, gate_A, p_topi, p_xau, p_xag);

    // hi/lo splits (coalesced, 8 elems/thread)
    {
        long long n8 = (long long)TOK * DMODEL / 8;
        cvt2_kernel<<<(unsigned)((n8 + 255) / 256), 256>>>(x, p_x_hi, p_x_lo, n8);
        n8 = (long long)HID * DMODEL / 8;
        cvt2_kernel<<<(unsigned)((n8 + 255) / 256), 256>>>(w_up, p_wup_hi, p_wup_lo, n8);
        cvt2_kernel<<<(unsigned)((n8 + 255) / 256), 256>>>(w_gate, p_wgate_hi, p_wgate_lo, n8);
        n8 = (long long)DMODEL * HID / 8;
        cvt2_kernel<<<(unsigned)((n8 + 255) / 256), 256>>>(w_down, p_wdown_hi, p_wdown_lo, n8);
    }

    // base up/gate projections on HMMA tensor cores
    {
        dim3 grid(HID / TN, TOK / TM);
        gemm_mma<false><<<grid, 256, GEMM_DSMEM>>>(p_x_hi, p_x_lo, p_wup_hi, p_wup_lo,
                                                   p_base_up, HID, DMODEL);
        gemm_mma<false><<<grid, 256, GEMM_DSMEM>>>(p_x_hi, p_x_lo, p_wgate_hi, p_wgate_lo,
                                                   p_base_gate, HID, DMODEL);
    }

    // fused SiLU-gate hidden + down-LoRA rank reduction (+ mixed hi/lo split)
    fused_hidden_kernel<<<TOK, 256>>>(up_B, gate_B, down_A);

    // lora_down -> out, then out += mixed @ w_down^T on HMMA
    lora_down_kernel<<<TOK, 256>>>(down_B, out);
    {
        dim3 grid(DMODEL / TN, TOK / TM);
        gemm_mma<true><<<grid, 256, GEMM_DSMEM>>>(p_mix_hi, p_mix_lo, p_wdown_hi, p_wdown_lo,
                                                  out, DMODEL, HID);
    }
}

// round 8
// speedup vs baseline: 2.1122x; 1.2626x over previous
#include <cuda_runtime.h>
#include <cuda_fp16.h>
#include <math_constants.h>
#include <cstdint>

// Problem dims (fixed by the dataset)
#define TOK    2048      // B*S = 2*1024
#define DMODEL 2048
#define HID    5632
#define NEXP   8
#define RANK   16
#define SEQ    1024
#define ALPHA  2.0f

// ---------------- scratch (static __device__ — no allocation allowed) -------
__device__ __align__(256) float g_base_up[TOK * HID];
__device__ __align__(256) float g_base_gate[TOK * HID];
__device__ __align__(256) float g_topv[TOK * 2];
__device__ __align__(256) int   g_topi[TOK * 2];
__device__ __align__(256) float g_wf[TOK * 2];
__device__ __align__(256) float g_xa_up[TOK * 2 * RANK];
__device__ __align__(256) float g_xa_gate[TOK * 2 * RANK];
__device__ __align__(256) float g_v[TOK * 2 * RANK];

// fp16 split operands: A-side exact (hi+lo), B-side rounded (hi only)
__device__ __align__(256) __half g_x_hi[(size_t)TOK * DMODEL];
__device__ __align__(256) __half g_x_lo[(size_t)TOK * DMODEL];
__device__ __align__(256) __half g_wup_hi[(size_t)HID * DMODEL];
__device__ __align__(256) __half g_wgate_hi[(size_t)HID * DMODEL];
__device__ __align__(256) __half g_wdown_hi[(size_t)DMODEL * HID];
__device__ __align__(256) __half g_mix_hi[(size_t)TOK * HID];
__device__ __align__(256) __half g_mix_lo[(size_t)TOK * HID];

// ---------------- helpers ----------------------------------------------------
__device__ __forceinline__ uint32_t smem_u32(const void* p) {
    uint32_t a;
    asm("{ .reg .u64 t; cvta.to.shared.u64 t, %1; cvt.u32.u64 %0, t; }"
        : "=r"(a) : "l"(p));
    return a;
}
__device__ __forceinline__ void cp16(uint32_t saddr, const void* gaddr) {
    asm volatile("cp.async.cg.shared.global [%0], [%1], 16;"
                 :: "r"(saddr), "l"(gaddr) : "memory");
}
__device__ __forceinline__ void cp_commit() {
    asm volatile("cp.async.commit_group;" ::: "memory");
}
template <int N>
__device__ __forceinline__ void cp_wait() {
    asm volatile("cp.async.wait_group %0;" :: "n"(N) : "memory");
}
__device__ __forceinline__ void ldsm_x4(uint32_t& r0, uint32_t& r1, uint32_t& r2,
                                        uint32_t& r3, uint32_t addr) {
    asm volatile("ldmatrix.sync.aligned.m8n8.x4.shared.b16 {%0,%1,%2,%3}, [%4];"
                 : "=r"(r0), "=r"(r1), "=r"(r2), "=r"(r3) : "r"(addr));
}
__device__ __forceinline__ void mma_f16(float* c, const uint32_t* a, const uint32_t* b) {
    asm volatile(
        "mma.sync.aligned.m16n8k16.row.col.f32.f16.f16.f32 "
        "{%0,%1,%2,%3}, {%4,%5,%6,%7}, {%8,%9}, {%0,%1,%2,%3};"
        : "+f"(c[0]), "+f"(c[1]), "+f"(c[2]), "+f"(c[3])
        : "r"(a[0]), "r"(a[1]), "r"(a[2]), "r"(a[3]), "r"(b[0]), "r"(b[1]));
}

// ---------------- router: logits + top-2 -------------------------------------
__global__ void router_kernel(const float* __restrict__ x,
                              const float* __restrict__ gw,
                              float* __restrict__ topv, int* __restrict__ topi) {
    int warp = threadIdx.x >> 5, lane = threadIdx.x & 31;
    int t = blockIdx.x * 8 + warp;
    const float* xr = x + (size_t)t * DMODEL;
    float p[NEXP];
#pragma unroll
    for (int e = 0; e < NEXP; e++) p[e] = 0.f;
    for (int d = lane; d < DMODEL; d += 32) {
        float xv = xr[d];
#pragma unroll
        for (int e = 0; e < NEXP; e++) p[e] = fmaf(xv, gw[e * DMODEL + d], p[e]);
    }
#pragma unroll
    for (int e = 0; e < NEXP; e++)
#pragma unroll
        for (int o = 16; o > 0; o >>= 1) p[e] += __shfl_xor_sync(~0u, p[e], o);
    if (lane == 0) {
        int i0 = 0; float v0 = p[0];
#pragma unroll
        for (int e = 1; e < NEXP; e++) if (p[e] > v0) { v0 = p[e]; i0 = e; }
        int i1 = -1; float v1 = -CUDART_INF_F;
#pragma unroll
        for (int e = 0; e < NEXP; e++) if (e != i0 && p[e] > v1) { v1 = p[e]; i1 = e; }
        topv[t * 2 + 0] = v0; topv[t * 2 + 1] = v1;
        topi[t * 2 + 0] = i0; topi[t * 2 + 1] = i1;
    }
}

// ---------------- softmax over the SEQUENCE axis per (batch, slot) ----------
__global__ void seq_softmax_kernel(const float* __restrict__ topv,
                                   float* __restrict__ wf) {
    int b = blockIdx.x >> 1, j = blockIdx.x & 1;
    int s = threadIdx.x;
    int lane = s & 31, warp = s >> 5;
    __shared__ float red[32];
    __shared__ float bc;
    float v = topv[(size_t)(b * SEQ + s) * 2 + j];
    float m = v;
#pragma unroll
    for (int o = 16; o > 0; o >>= 1) m = fmaxf(m, __shfl_xor_sync(~0u, m, o));
    if (lane == 0) red[warp] = m;
    __syncthreads();
    if (s < 32) {
        float mm = red[s];
#pragma unroll
        for (int o = 16; o > 0; o >>= 1) mm = fmaxf(mm, __shfl_xor_sync(~0u, mm, o));
        if (s == 0) bc = mm;
    }
    __syncthreads();
    float M = bc;
    float ev = __expf(v - M);
    float su = ev;
#pragma unroll
    for (int o = 16; o > 0; o >>= 1) su += __shfl_xor_sync(~0u, su, o);
    __syncthreads();
    if (lane == 0) red[warp] = su;
    __syncthreads();
    if (s < 32) {
        float ss = red[s];
#pragma unroll
        for (int o = 16; o > 0; o >>= 1) ss += __shfl_xor_sync(~0u, ss, o);
        if (s == 0) bc = ss;
    }
    __syncthreads();
    wf[(size_t)(b * SEQ + s) * 2 + j] = ev / bc;
}

// ---------------- per-token x @ A^T for the 2 selected experts --------------
__global__ void lora_xa_kernel(const float* __restrict__ x,
                               const float* __restrict__ upA,
                               const float* __restrict__ gateA,
                               const int* __restrict__ topi,
                               float* __restrict__ xaU, float* __restrict__ xaG) {
    int t = blockIdx.x;
    __shared__ float xs[DMODEL];
    __shared__ int es[2];
    int tid = threadIdx.x;
    const float4* xr4 = (const float4*)(x + (size_t)t * DMODEL);
    float4* xs4 = (float4*)xs;
#pragma unroll
    for (int i = tid; i < DMODEL / 4; i += 256) xs4[i] = xr4[i];
    if (tid < 2) es[tid] = topi[t * 2 + tid];
    __syncthreads();
    int warp = tid >> 5, lane = tid & 31;
    for (int jj = warp; jj < 64; jj += 8) {
        int j = jj >> 5;
        int which = (jj >> 4) & 1;
        int r = jj & 15;
        const float* Ar = (which ? gateA : upA) + ((size_t)es[j] * RANK + r) * DMODEL;
        float sacc = 0.f;
        for (int d = lane; d < DMODEL; d += 32) sacc = fmaf(xs[d], Ar[d], sacc);
#pragma unroll
        for (int o = 16; o > 0; o >>= 1) sacc += __shfl_xor_sync(~0u, sacc, o);
        if (lane == 0) (which ? xaG : xaU)[t * 2 * RANK + j * RANK + r] = sacc;
    }
}

// ---------------- fp32 -> fp16 hi-only (weights) ----------------------------
__global__ void cvt1_kernel(const float* __restrict__ src,
                            __half* __restrict__ hi, long long n8) {
    long long i = (long long)blockIdx.x * blockDim.x + threadIdx.x;
    if (i >= n8) return;
    const float4* s = (const float4*)src + i * 2;
    float4 a = s[0], b = s[1];
    float v[8] = {a.x, a.y, a.z, a.w, b.x, b.y, b.z, b.w};
    __half h[8];
#pragma unroll
    for (int q = 0; q < 8; q++) h[q] = __float2half(v[q]);
    *((uint4*)hi + i) = *(const uint4*)h;
}

// ---------------- fp32 -> fp16 hi/lo split (activations) --------------------
__global__ void cvt2_kernel(const float* __restrict__ src,
                            __half* __restrict__ hi,
                            __half* __restrict__ lo, long long n8) {
    long long i = (long long)blockIdx.x * blockDim.x + threadIdx.x;
    if (i >= n8) return;
    const float4* s = (const float4*)src + i * 2;
    float4 a = s[0], b = s[1];
    float v[8] = {a.x, a.y, a.z, a.w, b.x, b.y, b.z, b.w};
    __half h[8], l[8];
#pragma unroll
    for (int q = 0; q < 8; q++) {
        h[q] = __float2half(v[q]);
        l[q] = __float2half(v[q] - __half2float(h[q]));
    }
    *((uint4*)hi + i) = *(const uint4*)h;
    *((uint4*)lo + i) = *(const uint4*)l;
}

// ---------------- HMMA fp16x2 GEMM  C[M,N] (+)= A[M,K] B[N,K]^T -------------
// Phase walk: 0 = Ahi*Bhi, 1 = Alo*Bhi  ->  exact A times fl16(B)
// CTA 128x128, K-chunk 32, 4-stage cp.async pipeline, 8 warps (32x64 each).
#define TM 128
#define TN 128
#define TKC 32
#define ASTR 40           // row stride in fp16 elements (32 data + 8 pad)
#define STAGES 4
#define STG_ELEMS (TM * ASTR)

template <bool ADD_C>
__global__ __launch_bounds__(256, 2)
void gemm_mma(const __half* __restrict__ Ahi,
              const __half* __restrict__ Alo,
              const __half* __restrict__ Bhi,
              float* __restrict__ C, int N, int K) {
    extern __shared__ __half smem[];
    __half* sA = smem;                         // STAGES * STG_ELEMS
    __half* sB = smem + STAGES * STG_ELEMS;

    int tid = threadIdx.x;
    int wid = tid >> 5, lane = tid & 31;
    int wm = (wid >> 1) * 32;
    int wn = (wid & 1) * 64;

    int bm = blockIdx.y * TM;
    int bn = blockIdx.x * TN;
    int kchunks = K / TKC;
    int niter = 2 * kchunks;

    int lrow = tid >> 2;          // 0..63
    int lseg = tid & 3;

    uint32_t sA_u = smem_u32(sA);
    uint32_t sB_u = smem_u32(sB);

    auto load_stage = [&](int it) {
        int s = it & (STAGES - 1);
        int ph = (it >= kchunks);
        int k0 = (ph ? it - kchunks : it) * TKC;
        const __half* Asrc = (ph ? Alo : Ahi) + (size_t)bm * K + k0;
        const __half* Bsrc = Bhi + (size_t)bn * K + k0;
        uint32_t so = (uint32_t)(s * STG_ELEMS) * 2u;
#pragma unroll
        for (int h = 0; h < 2; h++) {
            int r = lrow + h * 64;
            uint32_t off = so + (uint32_t)(r * ASTR + lseg * 8) * 2u;
            cp16(sA_u + off, Asrc + (size_t)r * K + lseg * 8);
            cp16(sB_u + off, Bsrc + (size_t)r * K + lseg * 8);
        }
    };

    float acc[2][8][4];
#pragma unroll
    for (int mt = 0; mt < 2; mt++)
#pragma unroll
        for (int nt = 0; nt < 8; nt++)
#pragma unroll
            for (int q = 0; q < 4; q++) acc[mt][nt][q] = 0.f;

#pragma unroll
    for (int it = 0; it < STAGES - 1; it++) { load_stage(it); cp_commit(); }

    int lm = lane & 15;
    int lk = (lane >> 4) * 8;

    for (int it = 0; it < niter; it++) {
        cp_wait<STAGES - 2>();
        __syncthreads();
        if (it + STAGES - 1 < niter) load_stage(it + STAGES - 1);
        cp_commit();

        int s = it & (STAGES - 1);
        uint32_t sAo = sA_u + (uint32_t)(s * STG_ELEMS) * 2u;
        uint32_t sBo = sB_u + (uint32_t)(s * STG_ELEMS) * 2u;
#pragma unroll
        for (int kk = 0; kk < 2; kk++) {
            uint32_t a[2][4];
#pragma unroll
            for (int mt = 0; mt < 2; mt++) {
                uint32_t addr = sAo +
                    (uint32_t)((wm + mt * 16 + lm) * ASTR + kk * 16 + lk) * 2u;
                ldsm_x4(a[mt][0], a[mt][1], a[mt][2], a[mt][3], addr);
            }
            uint32_t b[8][2];
#pragma unroll
            for (int np = 0; np < 4; np++) {
                uint32_t r0, r1, r2, r3;
                uint32_t addr = sBo +
                    (uint32_t)((wn + np * 16 + lm) * ASTR + kk * 16 + lk) * 2u;
                ldsm_x4(r0, r1, r2, r3, addr);
                b[np * 2 + 0][0] = r0; b[np * 2 + 0][1] = r2;
                b[np * 2 + 1][0] = r1; b[np * 2 + 1][1] = r3;
            }
#pragma unroll
            for (int mt = 0; mt < 2; mt++)
#pragma unroll
                for (int nt = 0; nt < 8; nt++)
                    mma_f16(acc[mt][nt], a[mt], b[nt]);
        }
    }

    int rbase = bm + wm + (lane >> 2);
    int cbase = bn + wn + (lane & 3) * 2;
#pragma unroll
    for (int mt = 0; mt < 2; mt++) {
#pragma unroll
        for (int nt = 0; nt < 8; nt++) {
            float* p0 = C + (size_t)(rbase + mt * 16) * N + cbase + nt * 8;
            float* p1 = p0 + (size_t)8 * N;
            float2 v0 = make_float2(acc[mt][nt][0], acc[mt][nt][1]);
            float2 v1 = make_float2(acc[mt][nt][2], acc[mt][nt][3]);
            if (ADD_C) {
                float2 o0 = *(const float2*)p0;
                float2 o1 = *(const float2*)p1;
                v0.x += o0.x; v0.y += o0.y;
                v1.x += o1.x; v1.y += o1.y;
            }
            *(float2*)p0 = v0;
            *(float2*)p1 = v1;
        }
    }
}

// ---------------- fused SiLU-gate hidden + down-LoRA reduction --------------
// Emits mixed hidden directly as fp16 hi/lo (exact A-operand for down GEMM).
__global__ void fused_hidden_kernel(const float* __restrict__ upB,
                                    const float* __restrict__ gateB,
                                    const float* __restrict__ downA) {
    int t = blockIdx.x;
    int tid = threadIdx.x;
    int lane = tid & 31, warp = tid >> 5;
    __shared__ __align__(16) float sxu[2][16];
    __shared__ __align__(16) float sxg[2][16];
    __shared__ float sw[2];
    __shared__ int se[2];
    __shared__ float warpsum[8][32];

    if (tid < 32) {
        int j = tid >> 4, r = tid & 15;
        sxu[j][r] = g_xa_up[t * 32 + tid];
        sxg[j][r] = g_xa_gate[t * 32 + tid];
    }
    if (tid < 2) { sw[tid] = g_wf[t * 2 + tid]; se[tid] = g_topi[t * 2 + tid]; }
    __syncthreads();

    float vacc[2][16];
#pragma unroll
    for (int j = 0; j < 2; j++)
#pragma unroll
        for (int r = 0; r < 16; r++) vacc[j][r] = 0.f;

    int e0 = se[0], e1 = se[1];
    float w0 = sw[0], w1 = sw[1];

    for (int h = tid; h < HID; h += 256) {
        float bu = g_base_up[(size_t)t * HID + h];
        float bg = g_base_gate[(size_t)t * HID + h];
        float mix = 0.f;
#pragma unroll
        for (int j = 0; j < 2; j++) {
            int e = j ? e1 : e0;
            float w = j ? w1 : w0;
            const float4* ub = (const float4*)&upB[((size_t)e * HID + h) * RANK];
            const float4* gb = (const float4*)&gateB[((size_t)e * HID + h) * RANK];
            const float4* xu = (const float4*)sxu[j];
            const float4* xg = (const float4*)sxg[j];
            float lu = 0.f, lg = 0.f;
#pragma unroll
            for (int q = 0; q < 4; q++) {
                float4 u4 = ub[q], g4 = gb[q];
                float4 a4 = xu[q], c4 = xg[q];
                lu = fmaf(a4.x, u4.x, lu); lu = fmaf(a4.y, u4.y, lu);
                lu = fmaf(a4.z, u4.z, lu); lu = fmaf(a4.w, u4.w, lu);
                lg = fmaf(c4.x, g4.x, lg); lg = fmaf(c4.y, g4.y, lg);
                lg = fmaf(c4.z, g4.z, lg); lg = fmaf(c4.w, g4.w, lg);
            }
            float uu = bu + ALPHA * lu;
            float gg = bg + ALPHA * lg;
            float hv = uu / (1.f + __expf(-uu)) * gg;
            float ch = w * hv;
            mix += ch;
            const float* da = &downA[((size_t)e * RANK) * HID + h];
#pragma unroll
            for (int r = 0; r < 16; r++)
                vacc[j][r] = fmaf(ch, da[(size_t)r * HID], vacc[j][r]);
        }
        __half mh = __float2half(mix);
        g_mix_hi[(size_t)t * HID + h] = mh;
        g_mix_lo[(size_t)t * HID + h] = __float2half(mix - __half2float(mh));
    }

#pragma unroll
    for (int j = 0; j < 2; j++)
#pragma unroll
        for (int r = 0; r < 16; r++) {
            float s = vacc[j][r];
#pragma unroll
            for (int o = 16; o > 0; o >>= 1) s += __shfl_xor_sync(~0u, s, o);
            if (lane == 0) warpsum[warp][j * 16 + r] = s;
        }
    __syncthreads();
    if (tid < 32) {
        float s = 0.f;
#pragma unroll
        for (int w = 0; w < 8; w++) s += warpsum[w][tid];
        g_v[t * 32 + tid] = s;
    }
}

// ---------------- expand down-LoRA to [T, D] (writes d_out) -----------------
__global__ void lora_down_kernel(const float* __restrict__ downB,
                                 float* __restrict__ out) {
    int t = blockIdx.x;
    int tid = threadIdx.x;
    __shared__ __align__(16) float sv[2][16];
    __shared__ int se[2];
    if (tid < 32) sv[tid >> 4][tid & 15] = g_v[t * 32 + tid];
    if (tid < 2) se[tid] = g_topi[t * 2 + tid];
    __syncthreads();
    int e0 = se[0], e1 = se[1];
    for (int d = tid; d < DMODEL; d += 256) {
        float acc = 0.f;
#pragma unroll
        for (int j = 0; j < 2; j++) {
            int e = j ? e1 : e0;
            const float4* db = (const float4*)&downB[((size_t)e * DMODEL + d) * RANK];
            const float4* vv = (const float4*)sv[j];
#pragma unroll
            for (int q = 0; q < 4; q++) {
                float4 b4 = db[q], v4 = vv[q];
                acc = fmaf(v4.x, b4.x, acc); acc = fmaf(v4.y, b4.y, acc);
                acc = fmaf(v4.z, b4.z, acc); acc = fmaf(v4.w, b4.w, acc);
            }
        }
        out[(size_t)t * DMODEL + d] = ALPHA * acc;
    }
}

// ---------------- launch -----------------------------------------------------
#define GEMM_DSMEM (STAGES * STG_ELEMS * 2 * 2)   // A+B stages, fp16 = 81920 B

extern "C" void kernel_launch(void* const* d_in, const int* in_sizes, int n_in,
                              void* d_out, int out_size) {
    const float* x      = (const float*)d_in[0];
    const float* gate_w = (const float*)d_in[1];
    const float* w_up   = (const float*)d_in[2];
    const float* w_gate = (const float*)d_in[3];
    const float* w_down = (const float*)d_in[4];
    const float* up_A   = (const float*)d_in[5];
    const float* up_B   = (const float*)d_in[6];
    const float* gate_A = (const float*)d_in[7];
    const float* gate_B = (const float*)d_in[8];
    const float* down_A = (const float*)d_in[9];
    const float* down_B = (const float*)d_in[10];
    float* out = (float*)d_out;

    static float *p_base_up = nullptr, *p_base_gate = nullptr,
                 *p_topv = nullptr, *p_wf = nullptr, *p_xau = nullptr, *p_xag = nullptr;
    static int* p_topi = nullptr;
    static __half *p_x_hi, *p_x_lo, *p_wup_hi, *p_wgate_hi, *p_wdown_hi,
                  *p_mix_hi, *p_mix_lo;
    static bool inited = false;
    if (!inited) {
        cudaGetSymbolAddress((void**)&p_base_up, g_base_up);
        cudaGetSymbolAddress((void**)&p_base_gate, g_base_gate);
        cudaGetSymbolAddress((void**)&p_topv, g_topv);
        cudaGetSymbolAddress((void**)&p_topi, g_topi);
        cudaGetSymbolAddress((void**)&p_wf, g_wf);
        cudaGetSymbolAddress((void**)&p_xau, g_xa_up);
        cudaGetSymbolAddress((void**)&p_xag, g_xa_gate);
        cudaGetSymbolAddress((void**)&p_x_hi, g_x_hi);
        cudaGetSymbolAddress((void**)&p_x_lo, g_x_lo);
        cudaGetSymbolAddress((void**)&p_wup_hi, g_wup_hi);
        cudaGetSymbolAddress((void**)&p_wgate_hi, g_wgate_hi);
        cudaGetSymbolAddress((void**)&p_wdown_hi, g_wdown_hi);
        cudaGetSymbolAddress((void**)&p_mix_hi, g_mix_hi);
        cudaGetSymbolAddress((void**)&p_mix_lo, g_mix_lo);
        cudaFuncSetAttribute(gemm_mma<false>,
                             cudaFuncAttributeMaxDynamicSharedMemorySize, GEMM_DSMEM);
        cudaFuncSetAttribute(gemm_mma<true>,
                             cudaFuncAttributeMaxDynamicSharedMemorySize, GEMM_DSMEM);
        inited = true;
    }

    // Launch order chosen so launch index 5 (ncu -s 5 -c 1) is gemm_mma<false>.
    // #0-#2: weight hi conversions
    {
        long long n8 = (long long)HID * DMODEL / 8;
        cvt1_kernel<<<(unsigned)((n8 + 255) / 256), 256>>>(w_up, p_wup_hi, n8);
        cvt1_kernel<<<(unsigned)((n8 + 255) / 256), 256>>>(w_gate, p_wgate_hi, n8);
        n8 = (long long)DMODEL * HID / 8;
        cvt1_kernel<<<(unsigned)((n8 + 255) / 256), 256>>>(w_down, p_wdown_hi, n8);
    }
    // #3: activation hi/lo split
    {
        long long n8 = (long long)TOK * DMODEL / 8;
        cvt2_kernel<<<(unsigned)((n8 + 255) / 256), 256>>>(x, p_x_hi, p_x_lo, n8);
    }
    // #4: router
    router_kernel<<<TOK / 8, 256>>>(x, gate_w, p_topv, p_topi);
    // #5: up projection GEMM  <-- ncu capture target
    {
        dim3 grid(HID / TN, TOK / TM);
        gemm_mma<false><<<grid, 256, GEMM_DSMEM>>>(p_x_hi, p_x_lo, p_wup_hi,
                                                   p_base_up, HID, DMODEL);
    }
    // #6-#7: softmax + LoRA-A projections
    seq_softmax_kernel<<<4, SEQ>>>(p_topv, p_wf);
    lora_xa_kernel<<<TOK, 256>>>(x, up_A, gate_A, p_topi, p_xau, p_xag);
    // #8: gate projection GEMM
    {
        dim3 grid(HID / TN, TOK / TM);
        gemm_mma<false><<<grid, 256, GEMM_DSMEM>>>(p_x_hi, p_x_lo, p_wgate_hi,
                                                   p_base_gate, HID, DMODEL);
    }
    // #9: fused SiLU-gate hidden + down-LoRA rank reduction (+ mix hi/lo)
    fused_hidden_kernel<<<TOK, 256>>>(up_B, gate_B, down_A);
    // #10: lora_down -> out
    lora_down_kernel<<<TOK, 256>>>(down_B, out);
    // #11: out += mixed @ w_down^T
    {
        dim3 grid(DMODEL / TN, TOK / TM);
        gemm_mma<true><<<grid, 256, GEMM_DSMEM>>>(p_mix_hi, p_mix_lo, p_wdown_hi,
                                                  out, DMODEL, HID);
    }
}

// round 9
// speedup vs baseline: 2.6231x; 1.2419x over previous
#include <cuda_runtime.h>
#include <cuda_fp16.h>
#include <math_constants.h>
#include <cstdint>

// Problem dims (fixed by the dataset)
#define TOK    2048      // B*S = 2*1024
#define DMODEL 2048
#define HID    5632
#define NEXP   8
#define RANK   16
#define SEQ    1024
#define ALPHA  2.0f

// ---------------- scratch (static __device__ — no allocation allowed) -------
__device__ __align__(256) float g_base_up[TOK * HID];
__device__ __align__(256) float g_base_gate[TOK * HID];
__device__ __align__(256) float g_topv[TOK * 2];
__device__ __align__(256) int   g_topi[TOK * 2];
__device__ __align__(256) float g_wf[TOK * 2];
__device__ __align__(256) int   g_list[TOK * 2];
__device__ __align__(256) int   g_off[NEXP + 1];
__device__ __align__(256) float g_xa_part[4 * TOK * 256];      // K-split xa GEMM out
__device__ __align__(256) float g_ch0[(size_t)TOK * HID];      // slot-0 routed hidden
__device__ __align__(256) float g_ch1[(size_t)TOK * HID];      // slot-1 routed hidden
__device__ __align__(256) float g_vpart[4 * 2 * TOK * 128];    // K-split v GEMM out

// fp16 operands
__device__ __align__(256) __half g_x_hi[(size_t)TOK * DMODEL];
__device__ __align__(256) __half g_x_lo[(size_t)TOK * DMODEL];
__device__ __align__(256) __half g_wup_hi[(size_t)HID * DMODEL];
__device__ __align__(256) __half g_wgate_hi[(size_t)HID * DMODEL];
__device__ __align__(256) __half g_wdown_hi[(size_t)DMODEL * HID];
__device__ __align__(256) __half g_mix_hi[(size_t)TOK * HID];
__device__ __align__(256) __half g_mix_lo[(size_t)TOK * HID];
__device__ __align__(256) __half g_waall_hi[256 * DMODEL];     // [upA_all; gateA_all]
__device__ __align__(256) __half g_dAall_hi[128 * HID];        // downA_all
__device__ __align__(256) __half g_ch_h[(size_t)2 * TOK * HID];// stacked fp16 ch

// ---------------- helpers ----------------------------------------------------
__device__ __forceinline__ uint32_t smem_u32(const void* p) {
    uint32_t a;
    asm("{ .reg .u64 t; cvta.to.shared.u64 t, %1; cvt.u32.u64 %0, t; }"
        : "=r"(a) : "l"(p));
    return a;
}
__device__ __forceinline__ void cp16(uint32_t saddr, const void* gaddr) {
    asm volatile("cp.async.cg.shared.global [%0], [%1], 16;"
                 :: "r"(saddr), "l"(gaddr) : "memory");
}
__device__ __forceinline__ void cp_commit() {
    asm volatile("cp.async.commit_group;" ::: "memory");
}
template <int N>
__device__ __forceinline__ void cp_wait() {
    asm volatile("cp.async.wait_group %0;" :: "n"(N) : "memory");
}
__device__ __forceinline__ void ldsm_x4(uint32_t& r0, uint32_t& r1, uint32_t& r2,
                                        uint32_t& r3, uint32_t addr) {
    asm volatile("ldmatrix.sync.aligned.m8n8.x4.shared.b16 {%0,%1,%2,%3}, [%4];"
                 : "=r"(r0), "=r"(r1), "=r"(r2), "=r"(r3) : "r"(addr));
}
__device__ __forceinline__ void mma_f16(float* c, const uint32_t* a, const uint32_t* b) {
    asm volatile(
        "mma.sync.aligned.m16n8k16.row.col.f32.f16.f16.f32 "
        "{%0,%1,%2,%3}, {%4,%5,%6,%7}, {%8,%9}, {%0,%1,%2,%3};"
        : "+f"(c[0]), "+f"(c[1]), "+f"(c[2]), "+f"(c[3])
        : "r"(a[0]), "r"(a[1]), "r"(a[2]), "r"(a[3]), "r"(b[0]), "r"(b[1]));
}

// ---------------- router: logits + top-2 -------------------------------------
__global__ void router_kernel(const float* __restrict__ x,
                              const float* __restrict__ gw,
                              float* __restrict__ topv, int* __restrict__ topi) {
    int warp = threadIdx.x >> 5, lane = threadIdx.x & 31;
    int t = blockIdx.x * 8 + warp;
    const float* xr = x + (size_t)t * DMODEL;
    float p[NEXP];
#pragma unroll
    for (int e = 0; e < NEXP; e++) p[e] = 0.f;
    for (int d = lane; d < DMODEL; d += 32) {
        float xv = xr[d];
#pragma unroll
        for (int e = 0; e < NEXP; e++) p[e] = fmaf(xv, gw[e * DMODEL + d], p[e]);
    }
#pragma unroll
    for (int e = 0; e < NEXP; e++)
#pragma unroll
        for (int o = 16; o > 0; o >>= 1) p[e] += __shfl_xor_sync(~0u, p[e], o);
    if (lane == 0) {
        int i0 = 0; float v0 = p[0];
#pragma unroll
        for (int e = 1; e < NEXP; e++) if (p[e] > v0) { v0 = p[e]; i0 = e; }
        int i1 = -1; float v1 = -CUDART_INF_F;
#pragma unroll
        for (int e = 0; e < NEXP; e++) if (e != i0 && p[e] > v1) { v1 = p[e]; i1 = e; }
        topv[t * 2 + 0] = v0; topv[t * 2 + 1] = v1;
        topi[t * 2 + 0] = i0; topi[t * 2 + 1] = i1;
    }
}

// ---------------- softmax over the SEQUENCE axis per (batch, slot) ----------
__global__ void seq_softmax_kernel(const float* __restrict__ topv,
                                   float* __restrict__ wf) {
    int b = blockIdx.x >> 1, j = blockIdx.x & 1;
    int s = threadIdx.x;
    int lane = s & 31, warp = s >> 5;
    __shared__ float red[32];
    __shared__ float bc;
    float v = topv[(size_t)(b * SEQ + s) * 2 + j];
    float m = v;
#pragma unroll
    for (int o = 16; o > 0; o >>= 1) m = fmaxf(m, __shfl_xor_sync(~0u, m, o));
    if (lane == 0) red[warp] = m;
    __syncthreads();
    if (s < 32) {
        float mm = red[s];
#pragma unroll
        for (int o = 16; o > 0; o >>= 1) mm = fmaxf(mm, __shfl_xor_sync(~0u, mm, o));
        if (s == 0) bc = mm;
    }
    __syncthreads();
    float M = bc;
    float ev = __expf(v - M);
    float su = ev;
#pragma unroll
    for (int o = 16; o > 0; o >>= 1) su += __shfl_xor_sync(~0u, su, o);
    __syncthreads();
    if (lane == 0) red[warp] = su;
    __syncthreads();
    if (s < 32) {
        float ss = red[s];
#pragma unroll
        for (int o = 16; o > 0; o >>= 1) ss += __shfl_xor_sync(~0u, ss, o);
        if (s == 0) bc = ss;
    }
    __syncthreads();
    wf[(size_t)(b * SEQ + s) * 2 + j] = ev / bc;
}

// ---------------- route compaction (counts, offsets, expert lists) ----------
__global__ void route_compact_kernel(const int* __restrict__ topi,
                                     int* __restrict__ list, int* __restrict__ off) {
    __shared__ int scnt[NEXP], scur[NEXP];
    int tid = threadIdx.x;
    if (tid < NEXP) scnt[tid] = 0;
    __syncthreads();
    for (int i = tid; i < TOK * 2; i += 256) atomicAdd(&scnt[topi[i]], 1);
    __syncthreads();
    if (tid == 0) {
        int o = 0;
        for (int e = 0; e < NEXP; e++) { off[e] = o; scur[e] = o; o += scnt[e]; }
        off[NEXP] = o;
    }
    __syncthreads();
    for (int i = tid; i < TOK * 2; i += 256) {
        int p = atomicAdd(&scur[topi[i]], 1);
        list[p] = i;
    }
}

// ---------------- fp32 -> fp16 hi-only (weights) ----------------------------
__global__ void cvt1_kernel(const float* __restrict__ src,
                            __half* __restrict__ hi, long long n8) {
    long long i = (long long)blockIdx.x * blockDim.x + threadIdx.x;
    if (i >= n8) return;
    const float4* s = (const float4*)src + i * 2;
    float4 a = s[0], b = s[1];
    float v[8] = {a.x, a.y, a.z, a.w, b.x, b.y, b.z, b.w};
    __half h[8];
#pragma unroll
    for (int q = 0; q < 8; q++) h[q] = __float2half(v[q]);
    *((uint4*)hi + i) = *(const uint4*)h;
}

// ---------------- fp32 -> fp16 hi/lo split (activations) --------------------
__global__ void cvt2_kernel(const float* __restrict__ src,
                            __half* __restrict__ hi,
                            __half* __restrict__ lo, long long n8) {
    long long i = (long long)blockIdx.x * blockDim.x + threadIdx.x;
    if (i >= n8) return;
    const float4* s = (const float4*)src + i * 2;
    float4 a = s[0], b = s[1];
    float v[8] = {a.x, a.y, a.z, a.w, b.x, b.y, b.z, b.w};
    __half h[8], l[8];
#pragma unroll
    for (int q = 0; q < 8; q++) {
        h[q] = __float2half(v[q]);
        l[q] = __float2half(v[q] - __half2float(h[q]));
    }
    *((uint4*)hi + i) = *(const uint4*)h;
    *((uint4*)lo + i) = *(const uint4*)l;
}

// ---------------- HMMA GEMM  C[M,N] (+)= A[M,K] B[N,K]^T --------------------
// NPH=2: phases Ahi*B, Alo*B (exact A times fl16(B)). NPH=1: Ahi*B only.
// gridDim.z = K-split slices; slice z writes C + z*M*N (caller reduces).
#define TM 128
#define TN 128
#define TKC 32
#define ASTR 40
#define STAGES 4
#define STG_ELEMS (TM * ASTR)
#define GEMM_DSMEM (STAGES * STG_ELEMS * 2 * 2)   // 81920 B

template <bool ADD_C, int NPH>
__global__ __launch_bounds__(256, 2)
void gemm_mma(const __half* __restrict__ Ahi,
              const __half* __restrict__ Alo,
              const __half* __restrict__ Bhi,
              float* __restrict__ C, int M, int N, int K) {
    extern __shared__ __half smem[];
    __half* sA = smem;
    __half* sB = smem + STAGES * STG_ELEMS;

    int tid = threadIdx.x;
    int wid = tid >> 5, lane = tid & 31;
    int wm = (wid >> 1) * 32;
    int wn = (wid & 1) * 64;

    int Ks = K / gridDim.z;
    int kbase = blockIdx.z * Ks;
    C += (size_t)blockIdx.z * M * N;

    int bm = blockIdx.y * TM;
    int bn = blockIdx.x * TN;
    int kchunks = Ks / TKC;
    int niter = NPH * kchunks;

    int lrow = tid >> 2;
    int lseg = tid & 3;

    uint32_t sA_u = smem_u32(sA);
    uint32_t sB_u = smem_u32(sB);

    auto load_stage = [&](int it) {
        int s = it & (STAGES - 1);
        int ph = (NPH == 2) && (it >= kchunks);
        int k0 = kbase + (ph ? it - kchunks : it) * TKC;
        const __half* Asrc = (ph ? Alo : Ahi) + (size_t)bm * K + k0;
        const __half* Bsrc = Bhi + (size_t)bn * K + k0;
        uint32_t so = (uint32_t)(s * STG_ELEMS) * 2u;
#pragma unroll
        for (int h = 0; h < 2; h++) {
            int r = lrow + h * 64;
            uint32_t off = so + (uint32_t)(r * ASTR + lseg * 8) * 2u;
            cp16(sA_u + off, Asrc + (size_t)r * K + lseg * 8);
            cp16(sB_u + off, Bsrc + (size_t)r * K + lseg * 8);
        }
    };

    float acc[2][8][4];
#pragma unroll
    for (int mt = 0; mt < 2; mt++)
#pragma unroll
        for (int nt = 0; nt < 8; nt++)
#pragma unroll
            for (int q = 0; q < 4; q++) acc[mt][nt][q] = 0.f;

#pragma unroll
    for (int it = 0; it < STAGES - 1; it++) { load_stage(it); cp_commit(); }

    int lm = lane & 15;
    int lk = (lane >> 4) * 8;

    for (int it = 0; it < niter; it++) {
        cp_wait<STAGES - 2>();
        __syncthreads();
        if (it + STAGES - 1 < niter) load_stage(it + STAGES - 1);
        cp_commit();

        int s = it & (STAGES - 1);
        uint32_t sAo = sA_u + (uint32_t)(s * STG_ELEMS) * 2u;
        uint32_t sBo = sB_u + (uint32_t)(s * STG_ELEMS) * 2u;
#pragma unroll
        for (int kk = 0; kk < 2; kk++) {
            uint32_t a[2][4];
#pragma unroll
            for (int mt = 0; mt < 2; mt++) {
                uint32_t addr = sAo +
                    (uint32_t)((wm + mt * 16 + lm) * ASTR + kk * 16 + lk) * 2u;
                ldsm_x4(a[mt][0], a[mt][1], a[mt][2], a[mt][3], addr);
            }
            uint32_t b[8][2];
#pragma unroll
            for (int np = 0; np < 4; np++) {
                uint32_t r0, r1, r2, r3;
                uint32_t addr = sBo +
                    (uint32_t)((wn + np * 16 + lm) * ASTR + kk * 16 + lk) * 2u;
                ldsm_x4(r0, r1, r2, r3, addr);
                b[np * 2 + 0][0] = r0; b[np * 2 + 0][1] = r2;
                b[np * 2 + 1][0] = r1; b[np * 2 + 1][1] = r3;
            }
#pragma unroll
            for (int mt = 0; mt < 2; mt++)
#pragma unroll
                for (int nt = 0; nt < 8; nt++)
                    mma_f16(acc[mt][nt], a[mt], b[nt]);
        }
    }

    int rbase = bm + wm + (lane >> 2);
    int cbase = bn + wn + (lane & 3) * 2;
#pragma unroll
    for (int mt = 0; mt < 2; mt++) {
#pragma unroll
        for (int nt = 0; nt < 8; nt++) {
            float* p0 = C + (size_t)(rbase + mt * 16) * N + cbase + nt * 8;
            float* p1 = p0 + (size_t)8 * N;
            float2 v0 = make_float2(acc[mt][nt][0], acc[mt][nt][1]);
            float2 v1 = make_float2(acc[mt][nt][2], acc[mt][nt][3]);
            if (ADD_C) {
                float2 o0 = *(const float2*)p0;
                float2 o1 = *(const float2*)p1;
                v0.x += o0.x; v0.y += o0.y;
                v1.x += o1.x; v1.y += o1.y;
            }
            *(float2*)p0 = v0;
            *(float2*)p1 = v1;
        }
    }
}

// ---------------- expert-grouped routed hidden (ch per slot) ----------------
// grid 256: CTA = (expert e = bx&7, group g = bx>>3). Batches of 16 same-expert
// assignments; each lane keeps its h's upB/gateB rows in registers, reused
// across the 16 tokens.
__global__ __launch_bounds__(256)
void moe_hidden_kernel(const float* __restrict__ upB,
                       const float* __restrict__ gateB) {
    int e = blockIdx.x & 7;
    int g = blockIdx.x >> 3;
    int tid = threadIdx.x;
    int wid = tid >> 5, lane = tid & 31;

    __shared__ int st[16], sslot[16];
    __shared__ float sc[16];
    __shared__ __align__(16) float sxu[16][16];
    __shared__ __align__(16) float sxg[16][16];

    int o0 = g_off[e], cnt = g_off[e + 1] - o0;

    for (int base = g * 16; base < cnt; base += 32 * 16) {
        int nb = min(16, cnt - base);
        __syncthreads();
        if (tid < 16) {
            if (tid < nb) {
                int a = g_list[o0 + base + tid];
                st[tid] = a >> 1; sslot[tid] = a & 1; sc[tid] = g_wf[a];
            } else { st[tid] = 0; sslot[tid] = 0; sc[tid] = 0.f; }
        }
        __syncthreads();
        {
            int j = tid >> 4, r = tid & 15;
            int t = st[j];
            float su = 0.f, sg2 = 0.f;
#pragma unroll
            for (int z = 0; z < 4; z++) {
                su  += g_xa_part[((size_t)z * TOK + t) * 256 + e * 16 + r];
                sg2 += g_xa_part[((size_t)z * TOK + t) * 256 + 128 + e * 16 + r];
            }
            sxu[j][r] = su; sxg[j][r] = sg2;
        }
        __syncthreads();

        for (int hb = 0; hb < HID; hb += 256) {
            int h = hb + wid * 32 + lane;
            // lane's upB/gateB rows in registers
            float ub[16], gb[16];
            const float4* up4 = (const float4*)&upB[((size_t)e * HID + h) * RANK];
            const float4* gb4 = (const float4*)&gateB[((size_t)e * HID + h) * RANK];
#pragma unroll
            for (int q = 0; q < 4; q++) {
                float4 u = up4[q]; ub[q*4+0]=u.x; ub[q*4+1]=u.y; ub[q*4+2]=u.z; ub[q*4+3]=u.w;
                float4 gg = gb4[q]; gb[q*4+0]=gg.x; gb[q*4+1]=gg.y; gb[q*4+2]=gg.z; gb[q*4+3]=gg.w;
            }
            for (int j = 0; j < nb; j++) {
                int t = st[j];
                float bu = g_base_up[(size_t)t * HID + h];
                float bg = g_base_gate[(size_t)t * HID + h];
                float lu = 0.f, lg = 0.f;
#pragma unroll
                for (int r = 0; r < 16; r++) {
                    lu = fmaf(sxu[j][r], ub[r], lu);
                    lg = fmaf(sxg[j][r], gb[r], lg);
                }
                float uu = bu + ALPHA * lu;
                float gg = bg + ALPHA * lg;
                float ch = sc[j] * (uu / (1.f + __expf(-uu))) * gg;
                float* dst = sslot[j] ? g_ch1 : g_ch0;
                dst[(size_t)t * HID + h] = ch;
            }
        }
    }
}

// ---------------- combine: mix = ch0+ch1 -> fp16 hi/lo; ch -> fp16 ----------
__global__ void combine_kernel(long long n4) {
    long long i = (long long)blockIdx.x * blockDim.x + threadIdx.x;
    if (i >= n4) return;
    float4 c0 = *((const float4*)g_ch0 + i);
    float4 c1 = *((const float4*)g_ch1 + i);
    float m[4] = {c0.x + c1.x, c0.y + c1.y, c0.z + c1.z, c0.w + c1.w};
    __half h[4], l[4], h0[4], h1[4];
    float cc0[4] = {c0.x, c0.y, c0.z, c0.w};
    float cc1[4] = {c1.x, c1.y, c1.z, c1.w};
#pragma unroll
    for (int q = 0; q < 4; q++) {
        h[q] = __float2half(m[q]);
        l[q] = __float2half(m[q] - __half2float(h[q]));
        h0[q] = __float2half(cc0[q]);
        h1[q] = __float2half(cc1[q]);
    }
    *((uint2*)g_mix_hi + i) = *(const uint2*)h;
    *((uint2*)g_mix_lo + i) = *(const uint2*)l;
    *((uint2*)g_ch_h + i) = *(const uint2*)h0;
    *((uint2*)(g_ch_h + (size_t)TOK * HID) + i) = *(const uint2*)h1;
}

// ---------------- lora_down: out = ALPHA * (v_sel @ downB_sel^T) -------------
__global__ void lora_down_kernel(const float* __restrict__ downB,
                                 float* __restrict__ out) {
    int t = blockIdx.x;
    int tid = threadIdx.x;
    __shared__ __align__(16) float sv[2][16];
    __shared__ int se[2];
    if (tid < 2) se[tid] = g_topi[t * 2 + tid];
    __syncthreads();
    if (tid < 32) {
        int j = tid >> 4, r = tid & 15;
        int e = se[j];
        float s = 0.f;
#pragma unroll
        for (int z = 0; z < 4; z++)
            s += g_vpart[((size_t)z * 2 * TOK + (size_t)j * TOK + t) * 128 + e * 16 + r];
        sv[j][r] = s;
    }
    __syncthreads();
    int e0 = se[0], e1 = se[1];
    for (int d = tid; d < DMODEL; d += 256) {
        float acc = 0.f;
#pragma unroll
        for (int j = 0; j < 2; j++) {
            int e = j ? e1 : e0;
            const float4* db = (const float4*)&downB[((size_t)e * DMODEL + d) * RANK];
            const float4* vv = (const float4*)sv[j];
#pragma unroll
            for (int q = 0; q < 4; q++) {
                float4 b4 = db[q], v4 = vv[q];
                acc = fmaf(v4.x, b4.x, acc); acc = fmaf(v4.y, b4.y, acc);
                acc = fmaf(v4.z, b4.z, acc); acc = fmaf(v4.w, b4.w, acc);
            }
        }
        out[(size_t)t * DMODEL + d] = ALPHA * acc;
    }
}

// ---------------- launch -----------------------------------------------------
extern "C" void kernel_launch(void* const* d_in, const int* in_sizes, int n_in,
                              void* d_out, int out_size) {
    const float* x      = (const float*)d_in[0];
    const float* gate_w = (const float*)d_in[1];
    const float* w_up   = (const float*)d_in[2];
    const float* w_gate = (const float*)d_in[3];
    const float* w_down = (const float*)d_in[4];
    const float* up_A   = (const float*)d_in[5];
    const float* up_B   = (const float*)d_in[6];
    const float* gate_A = (const float*)d_in[7];
    const float* gate_B = (const float*)d_in[8];
    const float* down_A = (const float*)d_in[9];
    const float* down_B = (const float*)d_in[10];
    float* out = (float*)d_out;

    static float *p_base_up, *p_base_gate, *p_topv, *p_wf, *p_xa, *p_ch0, *p_ch1, *p_vp;
    static int *p_topi, *p_list, *p_off;
    static __half *p_x_hi, *p_x_lo, *p_wup_hi, *p_wgate_hi, *p_wdown_hi,
                  *p_mix_hi, *p_mix_lo, *p_waall, *p_dAall, *p_chh;
    static bool inited = false;
    if (!inited) {
        cudaGetSymbolAddress((void**)&p_base_up, g_base_up);
        cudaGetSymbolAddress((void**)&p_base_gate, g_base_gate);
        cudaGetSymbolAddress((void**)&p_topv, g_topv);
        cudaGetSymbolAddress((void**)&p_topi, g_topi);
        cudaGetSymbolAddress((void**)&p_wf, g_wf);
        cudaGetSymbolAddress((void**)&p_list, g_list);
        cudaGetSymbolAddress((void**)&p_off, g_off);
        cudaGetSymbolAddress((void**)&p_xa, g_xa_part);
        cudaGetSymbolAddress((void**)&p_ch0, g_ch0);
        cudaGetSymbolAddress((void**)&p_ch1, g_ch1);
        cudaGetSymbolAddress((void**)&p_vp, g_vpart);
        cudaGetSymbolAddress((void**)&p_x_hi, g_x_hi);
        cudaGetSymbolAddress((void**)&p_x_lo, g_x_lo);
        cudaGetSymbolAddress((void**)&p_wup_hi, g_wup_hi);
        cudaGetSymbolAddress((void**)&p_wgate_hi, g_wgate_hi);
        cudaGetSymbolAddress((void**)&p_wdown_hi, g_wdown_hi);
        cudaGetSymbolAddress((void**)&p_mix_hi, g_mix_hi);
        cudaGetSymbolAddress((void**)&p_mix_lo, g_mix_lo);
        cudaGetSymbolAddress((void**)&p_waall, g_waall_hi);
        cudaGetSymbolAddress((void**)&p_dAall, g_dAall_hi);
        cudaGetSymbolAddress((void**)&p_chh, g_ch_h);
        cudaFuncSetAttribute((const void*)gemm_mma<false, 2>,
                             cudaFuncAttributeMaxDynamicSharedMemorySize, GEMM_DSMEM);
        cudaFuncSetAttribute((const void*)gemm_mma<true, 2>,
                             cudaFuncAttributeMaxDynamicSharedMemorySize, GEMM_DSMEM);
        cudaFuncSetAttribute((const void*)gemm_mma<false, 1>,
                             cudaFuncAttributeMaxDynamicSharedMemorySize, GEMM_DSMEM);
        inited = true;
    }

    // conversions
    {
        long long n8 = (long long)HID * DMODEL / 8;
        cvt1_kernel<<<(unsigned)((n8 + 255) / 256), 256>>>(w_up, p_wup_hi, n8);
        cvt1_kernel<<<(unsigned)((n8 + 255) / 256), 256>>>(w_gate, p_wgate_hi, n8);
        n8 = (long long)DMODEL * HID / 8;
        cvt1_kernel<<<(unsigned)((n8 + 255) / 256), 256>>>(w_down, p_wdown_hi, n8);
        n8 = (long long)TOK * DMODEL / 8;
        cvt2_kernel<<<(unsigned)((n8 + 255) / 256), 256>>>(x, p_x_hi, p_x_lo, n8);
        n8 = (long long)128 * DMODEL / 8;
        cvt1_kernel<<<(unsigned)((n8 + 255) / 256), 256>>>(up_A, p_waall, n8);
        cvt1_kernel<<<(unsigned)((n8 + 255) / 256), 256>>>(gate_A, p_waall + 128 * DMODEL, n8);
        n8 = (long long)128 * HID / 8;
        cvt1_kernel<<<(unsigned)((n8 + 255) / 256), 256>>>(down_A, p_dAall, n8);
    }
    // routing
    router_kernel<<<TOK / 8, 256>>>(x, gate_w, p_topv, p_topi);
    route_compact_kernel<<<1, 256>>>(p_topi, p_list, p_off);
    seq_softmax_kernel<<<4, SEQ>>>(p_topv, p_wf);
    // xa_all = x @ [upA_all; gateA_all]^T  (K-split x4)
    {
        dim3 grid(256 / TN, TOK / TM, 4);
        gemm_mma<false, 2><<<grid, 256, GEMM_DSMEM>>>(p_x_hi, p_x_lo, p_waall,
                                                      p_xa, TOK, 256, DMODEL);
    }
    // base up/gate projections
    {
        dim3 grid(HID / TN, TOK / TM, 1);
        gemm_mma<false, 2><<<grid, 256, GEMM_DSMEM>>>(p_x_hi, p_x_lo, p_wup_hi,
                                                      p_base_up, TOK, HID, DMODEL);
        gemm_mma<false, 2><<<grid, 256, GEMM_DSMEM>>>(p_x_hi, p_x_lo, p_wgate_hi,
                                                      p_base_gate, TOK, HID, DMODEL);
    }
    // expert-grouped routed hidden -> ch0, ch1
    moe_hidden_kernel<<<256, 256>>>(up_B, gate_B);
    // combine -> mix hi/lo + fp16 ch
    {
        long long n4 = (long long)TOK * HID / 4;
        combine_kernel<<<(unsigned)((n4 + 255) / 256), 256>>>(n4);
    }
    // v = [ch0; ch1] @ downA_all^T  (stacked M=4096, K-split x4)
    {
        dim3 grid(128 / TN, 2 * TOK / TM, 4);
        gemm_mma<false, 1><<<grid, 256, GEMM_DSMEM>>>(p_chh, p_chh, p_dAall,
                                                      p_vp, 2 * TOK, 128, HID);
    }
    // lora_down -> out, then out += mixed @ w_down^T
    lora_down_kernel<<<TOK, 256>>>(down_B, out);
    {
        dim3 grid(DMODEL / TN, TOK / TM, 1);
        gemm_mma<true, 2><<<grid, 256, GEMM_DSMEM>>>(p_mix_hi, p_mix_lo, p_wdown_hi,
                                                     out, TOK, DMODEL, HID);
    }
}

// round 13
// speedup vs baseline: 2.6672x; 1.0168x over previous
#include <cuda_runtime.h>
#include <cuda_fp16.h>
#include <math_constants.h>
#include <cstdint>

// Problem dims (fixed by the dataset)
#define TOK    2048      // B*S = 2*1024
#define DMODEL 2048
#define HID    5632
#define NEXP   8
#define RANK   16
#define SEQ    1024
#define ALPHA  2.0f

// ---------------- scratch (static __device__ — no allocation allowed) -------
__device__ __align__(256) float g_base_up[TOK * HID];
__device__ __align__(256) float g_base_gate[TOK * HID];
__device__ __align__(256) float g_topv[TOK * 2];
__device__ __align__(256) int   g_topi[TOK * 2];
__device__ __align__(256) float g_wf[TOK * 2];
__device__ __align__(256) int   g_list[TOK * 2];
__device__ __align__(256) int   g_off[NEXP + 1];
__device__ __align__(256) float g_xa_part[4 * TOK * 256];      // K-split xa GEMM out
__device__ __align__(256) float g_ch0[(size_t)TOK * HID];      // slot-0 routed hidden
__device__ __align__(256) float g_ch1[(size_t)TOK * HID];      // slot-1 routed hidden
__device__ __align__(256) float g_vpart[4 * 2 * TOK * 128];    // K-split v GEMM out

// fp16 operands (single-rounded; error budget ~5.6e-4 total, threshold 1e-3)
__device__ __align__(256) __half g_x_hi[(size_t)TOK * DMODEL];
__device__ __align__(256) __half g_wup_hi[(size_t)HID * DMODEL];
__device__ __align__(256) __half g_wgate_hi[(size_t)HID * DMODEL];
__device__ __align__(256) __half g_wdown_hi[(size_t)DMODEL * HID];
__device__ __align__(256) __half g_mix_hi[(size_t)TOK * HID];
__device__ __align__(256) __half g_waall_hi[256 * DMODEL];     // [upA_all; gateA_all]
__device__ __align__(256) __half g_dAall_hi[128 * HID];        // downA_all
__device__ __align__(256) __half g_ch_h[(size_t)2 * TOK * HID];// stacked fp16 ch

// ---------------- helpers ----------------------------------------------------
__device__ __forceinline__ uint32_t smem_u32(const void* p) {
    uint32_t a;
    asm("{ .reg .u64 t; cvta.to.shared.u64 t, %1; cvt.u32.u64 %0, t; }"
        : "=r"(a) : "l"(p));
    return a;
}
__device__ __forceinline__ void cp16(uint32_t saddr, const void* gaddr) {
    asm volatile("cp.async.cg.shared.global [%0], [%1], 16;"
                 :: "r"(saddr), "l"(gaddr) : "memory");
}
__device__ __forceinline__ void cp_commit() {
    asm volatile("cp.async.commit_group;" ::: "memory");
}
template <int N>
__device__ __forceinline__ void cp_wait() {
    asm volatile("cp.async.wait_group %0;" :: "n"(N) : "memory");
}
__device__ __forceinline__ void ldsm_x4(uint32_t& r0, uint32_t& r1, uint32_t& r2,
                                        uint32_t& r3, uint32_t addr) {
    asm volatile("ldmatrix.sync.aligned.m8n8.x4.shared.b16 {%0,%1,%2,%3}, [%4];"
                 : "=r"(r0), "=r"(r1), "=r"(r2), "=r"(r3) : "r"(addr));
}
__device__ __forceinline__ void mma_f16(float* c, const uint32_t* a, const uint32_t* b) {
    asm volatile(
        "mma.sync.aligned.m16n8k16.row.col.f32.f16.f16.f32 "
        "{%0,%1,%2,%3}, {%4,%5,%6,%7}, {%8,%9}, {%0,%1,%2,%3};"
        : "+f"(c[0]), "+f"(c[1]), "+f"(c[2]), "+f"(c[3])
        : "r"(a[0]), "r"(a[1]), "r"(a[2]), "r"(a[3]), "r"(b[0]), "r"(b[1]));
}

// ---------------- router: logits + top-2 -------------------------------------
__global__ void router_kernel(const float* __restrict__ x,
                              const float* __restrict__ gw,
                              float* __restrict__ topv, int* __restrict__ topi) {
    int warp = threadIdx.x >> 5, lane = threadIdx.x & 31;
    int t = blockIdx.x * 8 + warp;
    const float* xr = x + (size_t)t * DMODEL;
    float p[NEXP];
#pragma unroll
    for (int e = 0; e < NEXP; e++) p[e] = 0.f;
    for (int d = lane; d < DMODEL; d += 32) {
        float xv = xr[d];
#pragma unroll
        for (int e = 0; e < NEXP; e++) p[e] = fmaf(xv, gw[e * DMODEL + d], p[e]);
    }
#pragma unroll
    for (int e = 0; e < NEXP; e++)
#pragma unroll
        for (int o = 16; o > 0; o >>= 1) p[e] += __shfl_xor_sync(~0u, p[e], o);
    if (lane == 0) {
        int i0 = 0; float v0 = p[0];
#pragma unroll
        for (int e = 1; e < NEXP; e++) if (p[e] > v0) { v0 = p[e]; i0 = e; }
        int i1 = -1; float v1 = -CUDART_INF_F;
#pragma unroll
        for (int e = 0; e < NEXP; e++) if (e != i0 && p[e] > v1) { v1 = p[e]; i1 = e; }
        topv[t * 2 + 0] = v0; topv[t * 2 + 1] = v1;
        topi[t * 2 + 0] = i0; topi[t * 2 + 1] = i1;
    }
}

// ---------------- softmax over the SEQUENCE axis per (batch, slot) ----------
__global__ void seq_softmax_kernel(const float* __restrict__ topv,
                                   float* __restrict__ wf) {
    int b = blockIdx.x >> 1, j = blockIdx.x & 1;
    int s = threadIdx.x;
    int lane = s & 31, warp = s >> 5;
    __shared__ float red[32];
    __shared__ float bc;
    float v = topv[(size_t)(b * SEQ + s) * 2 + j];
    float m = v;
#pragma unroll
    for (int o = 16; o > 0; o >>= 1) m = fmaxf(m, __shfl_xor_sync(~0u, m, o));
    if (lane == 0) red[warp] = m;
    __syncthreads();
    if (s < 32) {
        float mm = red[s];
#pragma unroll
        for (int o = 16; o > 0; o >>= 1) mm = fmaxf(mm, __shfl_xor_sync(~0u, mm, o));
        if (s == 0) bc = mm;
    }
    __syncthreads();
    float M = bc;
    float ev = __expf(v - M);
    float su = ev;
#pragma unroll
    for (int o = 16; o > 0; o >>= 1) su += __shfl_xor_sync(~0u, su, o);
    __syncthreads();
    if (lane == 0) red[warp] = su;
    __syncthreads();
    if (s < 32) {
        float ss = red[s];
#pragma unroll
        for (int o = 16; o > 0; o >>= 1) ss += __shfl_xor_sync(~0u, ss, o);
        if (s == 0) bc = ss;
    }
    __syncthreads();
    wf[(size_t)(b * SEQ + s) * 2 + j] = ev / bc;
}

// ---------------- route compaction (counts, offsets, expert lists) ----------
__global__ void route_compact_kernel(const int* __restrict__ topi,
                                     int* __restrict__ list, int* __restrict__ off) {
    __shared__ int scnt[NEXP], scur[NEXP];
    int tid = threadIdx.x;
    if (tid < NEXP) scnt[tid] = 0;
    __syncthreads();
    for (int i = tid; i < TOK * 2; i += 256) atomicAdd(&scnt[topi[i]], 1);
    __syncthreads();
    if (tid == 0) {
        int o = 0;
        for (int e = 0; e < NEXP; e++) { off[e] = o; scur[e] = o; o += scnt[e]; }
        off[NEXP] = o;
    }
    __syncthreads();
    for (int i = tid; i < TOK * 2; i += 256) {
        int p = atomicAdd(&scur[topi[i]], 1);
        list[p] = i;
    }
}

// ---------------- fp32 -> fp16 (single rounding) ----------------------------
__global__ void cvt1_kernel(const float* __restrict__ src,
                            __half* __restrict__ hi, long long n8) {
    long long i = (long long)blockIdx.x * blockDim.x + threadIdx.x;
    if (i >= n8) return;
    const float4* s = (const float4*)src + i * 2;
    float4 a = s[0], b = s[1];
    float v[8] = {a.x, a.y, a.z, a.w, b.x, b.y, b.z, b.w};
    __half h[8];
#pragma unroll
    for (int q = 0; q < 8; q++) h[q] = __float2half(v[q]);
    *((uint4*)hi + i) = *(const uint4*)h;
}

// ---------------- HMMA GEMM  C[M,N] (+)= A[M,K] B[N,K]^T --------------------
// gridDim.z = K-split slices; slice z writes C + z*M*N (caller reduces).
#define TM 128
#define TN 128
#define TKC 32
#define ASTR 40
#define STAGES 4
#define STG_ELEMS (TM * ASTR)
#define GEMM_DSMEM (STAGES * STG_ELEMS * 2 * 2)   // 81920 B

template <bool ADD_C>
__global__ __launch_bounds__(256, 2)
void gemm_mma(const __half* __restrict__ A,
              const __half* __restrict__ B,
              float* __restrict__ C, int M, int N, int K) {
    extern __shared__ __half smem[];
    __half* sA = smem;
    __half* sB = smem + STAGES * STG_ELEMS;

    int tid = threadIdx.x;
    int wid = tid >> 5, lane = tid & 31;
    int wm = (wid >> 1) * 32;
    int wn = (wid & 1) * 64;

    int Ks = K / gridDim.z;
    int kbase = blockIdx.z * Ks;
    C += (size_t)blockIdx.z * M * N;

    int bm = blockIdx.y * TM;
    int bn = blockIdx.x * TN;
    int niter = Ks / TKC;

    int lrow = tid >> 2;
    int lseg = tid & 3;

    uint32_t sA_u = smem_u32(sA);
    uint32_t sB_u = smem_u32(sB);

    auto load_stage = [&](int it) {
        int s = it & (STAGES - 1);
        int k0 = kbase + it * TKC;
        const __half* Asrc = A + (size_t)bm * K + k0;
        const __half* Bsrc = B + (size_t)bn * K + k0;
        uint32_t so = (uint32_t)(s * STG_ELEMS) * 2u;
#pragma unroll
        for (int h = 0; h < 2; h++) {
            int r = lrow + h * 64;
            uint32_t off = so + (uint32_t)(r * ASTR + lseg * 8) * 2u;
            cp16(sA_u + off, Asrc + (size_t)r * K + lseg * 8);
            cp16(sB_u + off, Bsrc + (size_t)r * K + lseg * 8);
        }
    };

    float acc[2][8][4];
#pragma unroll
    for (int mt = 0; mt < 2; mt++)
#pragma unroll
        for (int nt = 0; nt < 8; nt++)
#pragma unroll
            for (int q = 0; q < 4; q++) acc[mt][nt][q] = 0.f;

#pragma unroll
    for (int it = 0; it < STAGES - 1; it++) { load_stage(it); cp_commit(); }

    int lm = lane & 15;
    int lk = (lane >> 4) * 8;

    for (int it = 0; it < niter; it++) {
        cp_wait<STAGES - 2>();
        __syncthreads();
        if (it + STAGES - 1 < niter) load_stage(it + STAGES - 1);
        cp_commit();

        int s = it & (STAGES - 1);
        uint32_t sAo = sA_u + (uint32_t)(s * STG_ELEMS) * 2u;
        uint32_t sBo = sB_u + (uint32_t)(s * STG_ELEMS) * 2u;
#pragma unroll
        for (int kk = 0; kk < 2; kk++) {
            uint32_t a[2][4];
#pragma unroll
            for (int mt = 0; mt < 2; mt++) {
                uint32_t addr = sAo +
                    (uint32_t)((wm + mt * 16 + lm) * ASTR + kk * 16 + lk) * 2u;
                ldsm_x4(a[mt][0], a[mt][1], a[mt][2], a[mt][3], addr);
            }
            uint32_t b[8][2];
#pragma unroll
            for (int np = 0; np < 4; np++) {
                uint32_t r0, r1, r2, r3;
                uint32_t addr = sBo +
                    (uint32_t)((wn + np * 16 + lm) * ASTR + kk * 16 + lk) * 2u;
                ldsm_x4(r0, r1, r2, r3, addr);
                b[np * 2 + 0][0] = r0; b[np * 2 + 0][1] = r2;
                b[np * 2 + 1][0] = r1; b[np * 2 + 1][1] = r3;
            }
#pragma unroll
            for (int mt = 0; mt < 2; mt++)
#pragma unroll
                for (int nt = 0; nt < 8; nt++)
                    mma_f16(acc[mt][nt], a[mt], b[nt]);
        }
    }

    int rbase = bm + wm + (lane >> 2);
    int cbase = bn + wn + (lane & 3) * 2;
#pragma unroll
    for (int mt = 0; mt < 2; mt++) {
#pragma unroll
        for (int nt = 0; nt < 8; nt++) {
            float* p0 = C + (size_t)(rbase + mt * 16) * N + cbase + nt * 8;
            float* p1 = p0 + (size_t)8 * N;
            float2 v0 = make_float2(acc[mt][nt][0], acc[mt][nt][1]);
            float2 v1 = make_float2(acc[mt][nt][2], acc[mt][nt][3]);
            if (ADD_C) {
                float2 o0 = *(const float2*)p0;
                float2 o1 = *(const float2*)p1;
                v0.x += o0.x; v0.y += o0.y;
                v1.x += o1.x; v1.y += o1.y;
            }
            *(float2*)p0 = v0;
            *(float2*)p1 = v1;
        }
    }
}

// ---------------- expert-grouped routed hidden (ch per slot) ----------------
__global__ __launch_bounds__(256)
void moe_hidden_kernel(const float* __restrict__ upB,
                       const float* __restrict__ gateB) {
    int e = blockIdx.x & 7;
    int g = blockIdx.x >> 3;
    int tid = threadIdx.x;
    int wid = tid >> 5, lane = tid & 31;

    __shared__ int st[16], sslot[16];
    __shared__ float sc[16];
    __shared__ __align__(16) float sxu[16][16];
    __shared__ __align__(16) float sxg[16][16];

    int o0 = g_off[e], cnt = g_off[e + 1] - o0;

    for (int base = g * 16; base < cnt; base += 32 * 16) {
        int nb = min(16, cnt - base);
        __syncthreads();
        if (tid < 16) {
            if (tid < nb) {
                int a = g_list[o0 + base + tid];
                st[tid] = a >> 1; sslot[tid] = a & 1; sc[tid] = g_wf[a];
            } else { st[tid] = 0; sslot[tid] = 0; sc[tid] = 0.f; }
        }
        __syncthreads();
        {
            int j = tid >> 4, r = tid & 15;
            int t = st[j];
            float su = 0.f, sg2 = 0.f;
#pragma unroll
            for (int z = 0; z < 4; z++) {
                su  += g_xa_part[((size_t)z * TOK + t) * 256 + e * 16 + r];
                sg2 += g_xa_part[((size_t)z * TOK + t) * 256 + 128 + e * 16 + r];
            }
            sxu[j][r] = su; sxg[j][r] = sg2;
        }
        __syncthreads();

        for (int hb = 0; hb < HID; hb += 256) {
            int h = hb + wid * 32 + lane;
            float ub[16], gb[16];
            const float4* up4 = (const float4*)&upB[((size_t)e * HID + h) * RANK];
            const float4* gb4 = (const float4*)&gateB[((size_t)e * HID + h) * RANK];
#pragma unroll
            for (int q = 0; q < 4; q++) {
                float4 u = up4[q]; ub[q*4+0]=u.x; ub[q*4+1]=u.y; ub[q*4+2]=u.z; ub[q*4+3]=u.w;
                float4 gg = gb4[q]; gb[q*4+0]=gg.x; gb[q*4+1]=gg.y; gb[q*4+2]=gg.z; gb[q*4+3]=gg.w;
            }
            for (int j = 0; j < nb; j++) {
                int t = st[j];
                float bu = g_base_up[(size_t)t * HID + h];
                float bg = g_base_gate[(size_t)t * HID + h];
                float lu = 0.f, lg = 0.f;
#pragma unroll
                for (int r = 0; r < 16; r++) {
                    lu = fmaf(sxu[j][r], ub[r], lu);
                    lg = fmaf(sxg[j][r], gb[r], lg);
                }
                float uu = bu + ALPHA * lu;
                float gg = bg + ALPHA * lg;
                float ch = sc[j] * (uu / (1.f + __expf(-uu))) * gg;
                float* dst = sslot[j] ? g_ch1 : g_ch0;
                dst[(size_t)t * HID + h] = ch;
            }
        }
    }
}

// ---------------- combine: mix = ch0+ch1 -> fp16; ch -> fp16 ----------------
__global__ void combine_kernel(long long n4) {
    long long i = (long long)blockIdx.x * blockDim.x + threadIdx.x;
    if (i >= n4) return;
    float4 c0 = *((const float4*)g_ch0 + i);
    float4 c1 = *((const float4*)g_ch1 + i);
    float m[4] = {c0.x + c1.x, c0.y + c1.y, c0.z + c1.z, c0.w + c1.w};
    __half h[4], h0[4], h1[4];
    float cc0[4] = {c0.x, c0.y, c0.z, c0.w};
    float cc1[4] = {c1.x, c1.y, c1.z, c1.w};
#pragma unroll
    for (int q = 0; q < 4; q++) {
        h[q] = __float2half(m[q]);
        h0[q] = __float2half(cc0[q]);
        h1[q] = __float2half(cc1[q]);
    }
    *((uint2*)g_mix_hi + i) = *(const uint2*)h;
    *((uint2*)g_ch_h + i) = *(const uint2*)h0;
    *((uint2*)(g_ch_h + (size_t)TOK * HID) + i) = *(const uint2*)h1;
}

// ---------------- lora_down: out = ALPHA * (v_sel @ downB_sel^T) -------------
__global__ void lora_down_kernel(const float* __restrict__ downB,
                                 float* __restrict__ out) {
    int t = blockIdx.x;
    int tid = threadIdx.x;
    __shared__ __align__(16) float sv[2][16];
    __shared__ int se[2];
    if (tid < 2) se[tid] = g_topi[t * 2 + tid];
    __syncthreads();
    if (tid < 32) {
        int j = tid >> 4, r = tid & 15;
        int e = se[j];
        float s = 0.f;
#pragma unroll
        for (int z = 0; z < 4; z++)
            s += g_vpart[((size_t)z * 2 * TOK + (size_t)j * TOK + t) * 128 + e * 16 + r];
        sv[j][r] = s;
    }
    __syncthreads();
    int e0 = se[0], e1 = se[1];
    for (int d = tid; d < DMODEL; d += 256) {
        float acc = 0.f;
#pragma unroll
        for (int j = 0; j < 2; j++) {
            int e = j ? e1 : e0;
            const float4* db = (const float4*)&downB[((size_t)e * DMODEL + d) * RANK];
            const float4* vv = (const float4*)sv[j];
#pragma unroll
            for (int q = 0; q < 4; q++) {
                float4 b4 = db[q], v4 = vv[q];
                acc = fmaf(v4.x, b4.x, acc); acc = fmaf(v4.y, b4.y, acc);
                acc = fmaf(v4.z, b4.z, acc); acc = fmaf(v4.w, b4.w, acc);
            }
        }
        out[(size_t)t * DMODEL + d] = ALPHA * acc;
    }
}

// ---------------- launch -----------------------------------------------------
extern "C" void kernel_launch(void* const* d_in, const int* in_sizes, int n_in,
                              void* d_out, int out_size) {
    const float* x      = (const float*)d_in[0];
    const float* gate_w = (const float*)d_in[1];
    const float* w_up   = (const float*)d_in[2];
    const float* w_gate = (const float*)d_in[3];
    const float* w_down = (const float*)d_in[4];
    const float* up_A   = (const float*)d_in[5];
    const float* up_B   = (const float*)d_in[6];
    const float* gate_A = (const float*)d_in[7];
    const float* gate_B = (const float*)d_in[8];
    const float* down_A = (const float*)d_in[9];
    const float* down_B = (const float*)d_in[10];
    float* out = (float*)d_out;

    static float *p_base_up, *p_base_gate, *p_topv, *p_wf, *p_xa, *p_ch0, *p_ch1, *p_vp;
    static int *p_topi, *p_list, *p_off;
    static __half *p_x_hi, *p_wup_hi, *p_wgate_hi, *p_wdown_hi,
                  *p_mix_hi, *p_waall, *p_dAall, *p_chh;
    static bool inited = false;
    if (!inited) {
        cudaGetSymbolAddress((void**)&p_base_up, g_base_up);
        cudaGetSymbolAddress((void**)&p_base_gate, g_base_gate);
        cudaGetSymbolAddress((void**)&p_topv, g_topv);
        cudaGetSymbolAddress((void**)&p_topi, g_topi);
        cudaGetSymbolAddress((void**)&p_wf, g_wf);
        cudaGetSymbolAddress((void**)&p_list, g_list);
        cudaGetSymbolAddress((void**)&p_off, g_off);
        cudaGetSymbolAddress((void**)&p_xa, g_xa_part);
        cudaGetSymbolAddress((void**)&p_ch0, g_ch0);
        cudaGetSymbolAddress((void**)&p_ch1, g_ch1);
        cudaGetSymbolAddress((void**)&p_vp, g_vpart);
        cudaGetSymbolAddress((void**)&p_x_hi, g_x_hi);
        cudaGetSymbolAddress((void**)&p_wup_hi, g_wup_hi);
        cudaGetSymbolAddress((void**)&p_wgate_hi, g_wgate_hi);
        cudaGetSymbolAddress((void**)&p_wdown_hi, g_wdown_hi);
        cudaGetSymbolAddress((void**)&p_mix_hi, g_mix_hi);
        cudaGetSymbolAddress((void**)&p_waall, g_waall_hi);
        cudaGetSymbolAddress((void**)&p_dAall, g_dAall_hi);
        cudaGetSymbolAddress((void**)&p_chh, g_ch_h);
        cudaFuncSetAttribute((const void*)gemm_mma<false>,
                             cudaFuncAttributeMaxDynamicSharedMemorySize, GEMM_DSMEM);
        cudaFuncSetAttribute((const void*)gemm_mma<true>,
                             cudaFuncAttributeMaxDynamicSharedMemorySize, GEMM_DSMEM);
        inited = true;
    }

    // #0-#3: big conversions
    {
        long long n8 = (long long)HID * DMODEL / 8;
        cvt1_kernel<<<(unsigned)((n8 + 255) / 256), 256>>>(w_up, p_wup_hi, n8);
        cvt1_kernel<<<(unsigned)((n8 + 255) / 256), 256>>>(w_gate, p_wgate_hi, n8);
        n8 = (long long)DMODEL * HID / 8;
        cvt1_kernel<<<(unsigned)((n8 + 255) / 256), 256>>>(w_down, p_wdown_hi, n8);
        n8 = (long long)TOK * DMODEL / 8;
        cvt1_kernel<<<(unsigned)((n8 + 255) / 256), 256>>>(x, p_x_hi, n8);
    }
    // #4: router
    router_kernel<<<TOK / 8, 256>>>(x, gate_w, p_topv, p_topi);
    // #5: up projection GEMM  <-- ncu capture target
    {
        dim3 grid(HID / TN, TOK / TM, 1);
        gemm_mma<false><<<grid, 256, GEMM_DSMEM>>>(p_x_hi, p_wup_hi,
                                                   p_base_up, TOK, HID, DMODEL);
    }
    // #6: gate projection GEMM
    {
        dim3 grid(HID / TN, TOK / TM, 1);
        gemm_mma<false><<<grid, 256, GEMM_DSMEM>>>(p_x_hi, p_wgate_hi,
                                                   p_base_gate, TOK, HID, DMODEL);
    }
    // #7-#9: LoRA-A conversions
    {
        long long n8 = (long long)128 * DMODEL / 8;
        cvt1_kernel<<<(unsigned)((n8 + 255) / 256), 256>>>(up_A, p_waall, n8);
        cvt1_kernel<<<(unsigned)((n8 + 255) / 256), 256>>>(gate_A, p_waall + 128 * DMODEL, n8);
        n8 = (long long)128 * HID / 8;
        cvt1_kernel<<<(unsigned)((n8 + 255) / 256), 256>>>(down_A, p_dAall, n8);
    }
    // #10-#11: routing finish
    route_compact_kernel<<<1, 256>>>(p_topi, p_list, p_off);
    seq_softmax_kernel<<<4, SEQ>>>(p_topv, p_wf);
    // #12: xa_all = x @ [upA_all; gateA_all]^T  (K-split x4)
    {
        dim3 grid(256 / TN, TOK / TM, 4);
        gemm_mma<false><<<grid, 256, GEMM_DSMEM>>>(p_x_hi, p_waall,
                                                   p_xa, TOK, 256, DMODEL);
    }
    // #13: expert-grouped routed hidden -> ch0, ch1
    moe_hidden_kernel<<<256, 256>>>(up_B, gate_B);
    // #14: combine -> mix fp16 + fp16 ch
    {
        long long n4 = (long long)TOK * HID / 4;
        combine_kernel<<<(unsigned)((n4 + 255) / 256), 256>>>(n4);
    }
    // #15: v = [ch0; ch1] @ downA_all^T  (stacked M=4096, K-split x4)
    {
        dim3 grid(128 / TN, 2 * TOK / TM, 4);
        gemm_mma<false><<<grid, 256, GEMM_DSMEM>>>(p_chh, p_dAall,
                                                   p_vp, 2 * TOK, 128, HID);
    }
    // #16: lora_down -> out
    lora_down_kernel<<<TOK, 256>>>(down_B, out);
    // #17: out += mixed @ w_down^T
    {
        dim3 grid(DMODEL / TN, TOK / TM, 1);
        gemm_mma<true><<<grid, 256, GEMM_DSMEM>>>(p_mix_hi, p_wdown_hi,
                                                  out, TOK, DMODEL, HID);
    }
}

// round 16
// speedup vs baseline: 4.0528x; 1.5195x over previous
#include <cuda_runtime.h>
#include <cuda_fp16.h>
#include <math_constants.h>
#include <cstdint>

// Problem dims (fixed by the dataset)
#define TOK    2048      // B*S = 2*1024
#define DMODEL 2048
#define HID    5632
#define NEXP   8
#define RANK   16
#define SEQ    1024
#define ALPHA  2.0f

// ---------------- scratch (static __device__ — no allocation allowed) -------
__device__ __align__(256) float g_topv[TOK * 2];
__device__ __align__(256) int   g_topi[TOK * 2];
__device__ __align__(256) float g_wf[TOK * 2];
__device__ __align__(256) int   g_list[TOK * 2];
__device__ __align__(256) int   g_off[NEXP + 1];
__device__ __align__(256) float g_xa_part[4 * TOK * 256];      // K-split xa GEMM out
__device__ __align__(256) float g_vpart[4 * 2 * TOK * 128];    // K-split v GEMM out

// fp16 operands / intermediates
__device__ __align__(256) __half g_x_hi[(size_t)TOK * DMODEL];
__device__ __align__(256) __half g_wup_hi[(size_t)HID * DMODEL];
__device__ __align__(256) __half g_wgate_hi[(size_t)HID * DMODEL];
__device__ __align__(256) __half g_wdown_hi[(size_t)DMODEL * HID];
__device__ __align__(256) __half g_base_up_h[(size_t)TOK * HID];
__device__ __align__(256) __half g_base_gate_h[(size_t)TOK * HID];
__device__ __align__(256) __half g_mix_hi[(size_t)TOK * HID];
__device__ __align__(256) __half g_waall_hi[256 * DMODEL];     // [upA_all; gateA_all]
__device__ __align__(256) __half g_dAall_hi[128 * HID];        // downA_all
__device__ __align__(256) __half g_ch_h[(size_t)2 * TOK * HID];// stacked fp16 ch (slot-major)

// ---------------- helpers ----------------------------------------------------
__device__ __forceinline__ uint32_t smem_u32(const void* p) {
    uint32_t a;
    asm("{ .reg .u64 t; cvta.to.shared.u64 t, %1; cvt.u32.u64 %0, t; }"
        : "=r"(a) : "l"(p));
    return a;
}
__device__ __forceinline__ void cp16(uint32_t saddr, const void* gaddr) {
    asm volatile("cp.async.cg.shared.global [%0], [%1], 16;"
                 :: "r"(saddr), "l"(gaddr) : "memory");
}
__device__ __forceinline__ void cp_commit() {
    asm volatile("cp.async.commit_group;" ::: "memory");
}
template <int N>
__device__ __forceinline__ void cp_wait() {
    asm volatile("cp.async.wait_group %0;" :: "n"(N) : "memory");
}
__device__ __forceinline__ void ldsm_x4(uint32_t& r0, uint32_t& r1, uint32_t& r2,
                                        uint32_t& r3, uint32_t addr) {
    asm volatile("ldmatrix.sync.aligned.m8n8.x4.shared.b16 {%0,%1,%2,%3}, [%4];"
                 : "=r"(r0), "=r"(r1), "=r"(r2), "=r"(r3) : "r"(addr));
}
__device__ __forceinline__ void mma_f16(float* c, const uint32_t* a, const uint32_t* b) {
    asm volatile(
        "mma.sync.aligned.m16n8k16.row.col.f32.f16.f16.f32 "
        "{%0,%1,%2,%3}, {%4,%5,%6,%7}, {%8,%9}, {%0,%1,%2,%3};"
        : "+f"(c[0]), "+f"(c[1]), "+f"(c[2]), "+f"(c[3])
        : "r"(a[0]), "r"(a[1]), "r"(a[2]), "r"(a[3]), "r"(b[0]), "r"(b[1]));
}

// ---------------- router: logits + top-2 -------------------------------------
__global__ void router_kernel(const float* __restrict__ x,
                              const float* __restrict__ gw,
                              float* __restrict__ topv, int* __restrict__ topi) {
    int warp = threadIdx.x >> 5, lane = threadIdx.x & 31;
    int t = blockIdx.x * 8 + warp;
    const float* xr = x + (size_t)t * DMODEL;
    float p[NEXP];
#pragma unroll
    for (int e = 0; e < NEXP; e++) p[e] = 0.f;
    for (int d = lane; d < DMODEL; d += 32) {
        float xv = xr[d];
#pragma unroll
        for (int e = 0; e < NEXP; e++) p[e] = fmaf(xv, gw[e * DMODEL + d], p[e]);
    }
#pragma unroll
    for (int e = 0; e < NEXP; e++)
#pragma unroll
        for (int o = 16; o > 0; o >>= 1) p[e] += __shfl_xor_sync(~0u, p[e], o);
    if (lane == 0) {
        int i0 = 0; float v0 = p[0];
#pragma unroll
        for (int e = 1; e < NEXP; e++) if (p[e] > v0) { v0 = p[e]; i0 = e; }
        int i1 = -1; float v1 = -CUDART_INF_F;
#pragma unroll
        for (int e = 0; e < NEXP; e++) if (e != i0 && p[e] > v1) { v1 = p[e]; i1 = e; }
        topv[t * 2 + 0] = v0; topv[t * 2 + 1] = v1;
        topi[t * 2 + 0] = i0; topi[t * 2 + 1] = i1;
    }
}

// ---------------- softmax over the SEQUENCE axis per (batch, slot) ----------
__global__ void seq_softmax_kernel(const float* __restrict__ topv,
                                   float* __restrict__ wf) {
    int b = blockIdx.x >> 1, j = blockIdx.x & 1;
    int s = threadIdx.x;
    int lane = s & 31, warp = s >> 5;
    __shared__ float red[32];
    __shared__ float bc;
    float v = topv[(size_t)(b * SEQ + s) * 2 + j];
    float m = v;
#pragma unroll
    for (int o = 16; o > 0; o >>= 1) m = fmaxf(m, __shfl_xor_sync(~0u, m, o));
    if (lane == 0) red[warp] = m;
    __syncthreads();
    if (s < 32) {
        float mm = red[s];
#pragma unroll
        for (int o = 16; o > 0; o >>= 1) mm = fmaxf(mm, __shfl_xor_sync(~0u, mm, o));
        if (s == 0) bc = mm;
    }
    __syncthreads();
    float M = bc;
    float ev = __expf(v - M);
    float su = ev;
#pragma unroll
    for (int o = 16; o > 0; o >>= 1) su += __shfl_xor_sync(~0u, su, o);
    __syncthreads();
    if (lane == 0) red[warp] = su;
    __syncthreads();
    if (s < 32) {
        float ss = red[s];
#pragma unroll
        for (int o = 16; o > 0; o >>= 1) ss += __shfl_xor_sync(~0u, ss, o);
        if (s == 0) bc = ss;
    }
    __syncthreads();
    wf[(size_t)(b * SEQ + s) * 2 + j] = ev / bc;
}

// ---------------- route compaction (counts, offsets, expert lists) ----------
__global__ void route_compact_kernel(const int* __restrict__ topi,
                                     int* __restrict__ list, int* __restrict__ off) {
    __shared__ int scnt[NEXP], scur[NEXP];
    int tid = threadIdx.x;
    if (tid < NEXP) scnt[tid] = 0;
    __syncthreads();
    for (int i = tid; i < TOK * 2; i += 256) atomicAdd(&scnt[topi[i]], 1);
    __syncthreads();
    if (tid == 0) {
        int o = 0;
        for (int e = 0; e < NEXP; e++) { off[e] = o; scur[e] = o; o += scnt[e]; }
        off[NEXP] = o;
    }
    __syncthreads();
    for (int i = tid; i < TOK * 2; i += 256) {
        int p = atomicAdd(&scur[topi[i]], 1);
        list[p] = i;
    }
}

// ---------------- fp32 -> fp16 (single rounding) ----------------------------
__global__ void cvt1_kernel(const float* __restrict__ src,
                            __half* __restrict__ hi, long long n8) {
    long long i = (long long)blockIdx.x * blockDim.x + threadIdx.x;
    if (i >= n8) return;
    const float4* s = (const float4*)src + i * 2;
    float4 a = s[0], b = s[1];
    float v[8] = {a.x, a.y, a.z, a.w, b.x, b.y, b.z, b.w};
    __half h[8];
#pragma unroll
    for (int q = 0; q < 8; q++) h[q] = __float2half(v[q]);
    *((uint4*)hi + i) = *(const uint4*)h;
}

// ---------------- HMMA GEMM  C[M,N] (+)= A[M,K] B[N,K]^T --------------------
// gridDim.z = K-split slices; slice z writes C + z*M*N (caller reduces).
// HALF_OUT: epilogue stores __half (no ADD_C support needed in that mode).
#define TM 128
#define TN 128
#define TKC 32
#define ASTR 40
#define STAGES 4
#define STG_ELEMS (TM * ASTR)
#define GEMM_DSMEM (STAGES * STG_ELEMS * 2 * 2)   // 81920 B

template <bool ADD_C, bool HALF_OUT>
__global__ __launch_bounds__(256, 2)
void gemm_mma(const __half* __restrict__ A,
              const __half* __restrict__ B,
              void* __restrict__ Cv, int M, int N, int K) {
    extern __shared__ __half smem[];
    __half* sA = smem;
    __half* sB = smem + STAGES * STG_ELEMS;

    int tid = threadIdx.x;
    int wid = tid >> 5, lane = tid & 31;
    int wm = (wid >> 1) * 32;
    int wn = (wid & 1) * 64;

    int Ks = K / gridDim.z;
    int kbase = blockIdx.z * Ks;

    int bm = blockIdx.y * TM;
    int bn = blockIdx.x * TN;
    int niter = Ks / TKC;

    int lrow = tid >> 2;
    int lseg = tid & 3;

    uint32_t sA_u = smem_u32(sA);
    uint32_t sB_u = smem_u32(sB);

    auto load_stage = [&](int it) {
        int s = it & (STAGES - 1);
        int k0 = kbase + it * TKC;
        const __half* Asrc = A + (size_t)bm * K + k0;
        const __half* Bsrc = B + (size_t)bn * K + k0;
        uint32_t so = (uint32_t)(s * STG_ELEMS) * 2u;
#pragma unroll
        for (int h = 0; h < 2; h++) {
            int r = lrow + h * 64;
            uint32_t off = so + (uint32_t)(r * ASTR + lseg * 8) * 2u;
            cp16(sA_u + off, Asrc + (size_t)r * K + lseg * 8);
            cp16(sB_u + off, Bsrc + (size_t)r * K + lseg * 8);
        }
    };

    float acc[2][8][4];
#pragma unroll
    for (int mt = 0; mt < 2; mt++)
#pragma unroll
        for (int nt = 0; nt < 8; nt++)
#pragma unroll
            for (int q = 0; q < 4; q++) acc[mt][nt][q] = 0.f;

#pragma unroll
    for (int it = 0; it < STAGES - 1; it++) { load_stage(it); cp_commit(); }

    int lm = lane & 15;
    int lk = (lane >> 4) * 8;

    for (int it = 0; it < niter; it++) {
        cp_wait<STAGES - 2>();
        __syncthreads();
        if (it + STAGES - 1 < niter) load_stage(it + STAGES - 1);
        cp_commit();

        int s = it & (STAGES - 1);
        uint32_t sAo = sA_u + (uint32_t)(s * STG_ELEMS) * 2u;
        uint32_t sBo = sB_u + (uint32_t)(s * STG_ELEMS) * 2u;
#pragma unroll
        for (int kk = 0; kk < 2; kk++) {
            uint32_t a[2][4];
#pragma unroll
            for (int mt = 0; mt < 2; mt++) {
                uint32_t addr = sAo +
                    (uint32_t)((wm + mt * 16 + lm) * ASTR + kk * 16 + lk) * 2u;
                ldsm_x4(a[mt][0], a[mt][1], a[mt][2], a[mt][3], addr);
            }
            uint32_t b[8][2];
#pragma unroll
            for (int np = 0; np < 4; np++) {
                uint32_t r0, r1, r2, r3;
                uint32_t addr = sBo +
                    (uint32_t)((wn + np * 16 + lm) * ASTR + kk * 16 + lk) * 2u;
                ldsm_x4(r0, r1, r2, r3, addr);
                b[np * 2 + 0][0] = r0; b[np * 2 + 0][1] = r2;
                b[np * 2 + 1][0] = r1; b[np * 2 + 1][1] = r3;
            }
#pragma unroll
            for (int mt = 0; mt < 2; mt++)
#pragma unroll
                for (int nt = 0; nt < 8; nt++)
                    mma_f16(acc[mt][nt], a[mt], b[nt]);
        }
    }

    int rbase = bm + wm + (lane >> 2);
    int cbase = bn + wn + (lane & 3) * 2;
    if (HALF_OUT) {
        __half* C = (__half*)Cv + (size_t)blockIdx.z * M * N;
#pragma unroll
        for (int mt = 0; mt < 2; mt++) {
#pragma unroll
            for (int nt = 0; nt < 8; nt++) {
                __half* p0 = C + (size_t)(rbase + mt * 16) * N + cbase + nt * 8;
                __half* p1 = p0 + (size_t)8 * N;
                __half2 v0 = __floats2half2_rn(acc[mt][nt][0], acc[mt][nt][1]);
                __half2 v1 = __floats2half2_rn(acc[mt][nt][2], acc[mt][nt][3]);
                *(__half2*)p0 = v0;
                *(__half2*)p1 = v1;
            }
        }
    } else {
        float* C = (float*)Cv + (size_t)blockIdx.z * M * N;
#pragma unroll
        for (int mt = 0; mt < 2; mt++) {
#pragma unroll
            for (int nt = 0; nt < 8; nt++) {
                float* p0 = C + (size_t)(rbase + mt * 16) * N + cbase + nt * 8;
                float* p1 = p0 + (size_t)8 * N;
                float2 v0 = make_float2(acc[mt][nt][0], acc[mt][nt][1]);
                float2 v1 = make_float2(acc[mt][nt][2], acc[mt][nt][3]);
                if (ADD_C) {
                    float2 o0 = *(const float2*)p0;
                    float2 o1 = *(const float2*)p1;
                    v0.x += o0.x; v0.y += o0.y;
                    v1.x += o1.x; v1.y += o1.y;
                }
                *(float2*)p0 = v0;
                *(float2*)p1 = v1;
            }
        }
    }
}

// ---------------- expert-grouped routed hidden (fp16 ch out) ----------------
__global__ __launch_bounds__(256)
void moe_hidden_kernel(const float* __restrict__ upB,
                       const float* __restrict__ gateB) {
    int e = blockIdx.x & 7;
    int g = blockIdx.x >> 3;
    int tid = threadIdx.x;
    int wid = tid >> 5, lane = tid & 31;

    __shared__ int st[16], sslot[16];
    __shared__ float sc[16];
    __shared__ __align__(16) float sxu[16][16];
    __shared__ __align__(16) float sxg[16][16];

    int o0 = g_off[e], cnt = g_off[e + 1] - o0;

    for (int base = g * 16; base < cnt; base += 32 * 16) {
        int nb = min(16, cnt - base);
        __syncthreads();
        if (tid < 16) {
            if (tid < nb) {
                int a = g_list[o0 + base + tid];
                st[tid] = a >> 1; sslot[tid] = a & 1; sc[tid] = g_wf[a];
            } else { st[tid] = 0; sslot[tid] = 0; sc[tid] = 0.f; }
        }
        __syncthreads();
        {
            int j = tid >> 4, r = tid & 15;
            int t = st[j];
            float su = 0.f, sg2 = 0.f;
#pragma unroll
            for (int z = 0; z < 4; z++) {
                su  += g_xa_part[((size_t)z * TOK + t) * 256 + e * 16 + r];
                sg2 += g_xa_part[((size_t)z * TOK + t) * 256 + 128 + e * 16 + r];
            }
            sxu[j][r] = su; sxg[j][r] = sg2;
        }
        __syncthreads();

        for (int hb = 0; hb < HID; hb += 256) {
            int h = hb + wid * 32 + lane;
            float ub[16], gb[16];
            const float4* up4 = (const float4*)&upB[((size_t)e * HID + h) * RANK];
            const float4* gb4 = (const float4*)&gateB[((size_t)e * HID + h) * RANK];
#pragma unroll
            for (int q = 0; q < 4; q++) {
                float4 u = up4[q]; ub[q*4+0]=u.x; ub[q*4+1]=u.y; ub[q*4+2]=u.z; ub[q*4+3]=u.w;
                float4 gg = gb4[q]; gb[q*4+0]=gg.x; gb[q*4+1]=gg.y; gb[q*4+2]=gg.z; gb[q*4+3]=gg.w;
            }
            for (int j = 0; j < nb; j++) {
                int t = st[j];
                float bu = __half2float(g_base_up_h[(size_t)t * HID + h]);
                float bg = __half2float(g_base_gate_h[(size_t)t * HID + h]);
                float lu = 0.f, lg = 0.f;
#pragma unroll
                for (int r = 0; r < 16; r++) {
                    lu = fmaf(sxu[j][r], ub[r], lu);
                    lg = fmaf(sxg[j][r], gb[r], lg);
                }
                float uu = bu + ALPHA * lu;
                float gg = bg + ALPHA * lg;
                float ch = sc[j] * (uu / (1.f + __expf(-uu))) * gg;
                g_ch_h[((size_t)sslot[j] * TOK + t) * HID + h] = __float2half(ch);
            }
        }
    }
}

// ---------------- combine: mix = ch0+ch1 (fp16 in, fp16 out) ----------------
__global__ void combine_kernel(long long n8) {
    long long i = (long long)blockIdx.x * blockDim.x + threadIdx.x;
    if (i >= n8) return;
    uint4 u0 = *((const uint4*)g_ch_h + i);
    uint4 u1 = *((const uint4*)(g_ch_h + (size_t)TOK * HID) + i);
    const __half2* a = (const __half2*)&u0;
    const __half2* b = (const __half2*)&u1;
    uint4 o;
    __half2* ov = (__half2*)&o;
#pragma unroll
    for (int q = 0; q < 4; q++) {
        float2 fa = __half22float2(a[q]);
        float2 fb = __half22float2(b[q]);
        ov[q] = __floats2half2_rn(fa.x + fb.x, fa.y + fb.y);
    }
    *((uint4*)g_mix_hi + i) = o;
}

// ---------------- lora_down: out = ALPHA * (v_sel @ downB_sel^T) -------------
__global__ void lora_down_kernel(const float* __restrict__ downB,
                                 float* __restrict__ out) {
    int t = blockIdx.x;
    int tid = threadIdx.x;
    __shared__ __align__(16) float sv[2][16];
    __shared__ int se[2];
    if (tid < 2) se[tid] = g_topi[t * 2 + tid];
    __syncthreads();
    if (tid < 32) {
        int j = tid >> 4, r = tid & 15;
        int e = se[j];
        float s = 0.f;
#pragma unroll
        for (int z = 0; z < 4; z++)
            s += g_vpart[((size_t)z * 2 * TOK + (size_t)j * TOK + t) * 128 + e * 16 + r];
        sv[j][r] = s;
    }
    __syncthreads();
    int e0 = se[0], e1 = se[1];
    for (int d = tid; d < DMODEL; d += 256) {
        float acc = 0.f;
#pragma unroll
        for (int j = 0; j < 2; j++) {
            int e = j ? e1 : e0;
            const float4* db = (const float4*)&downB[((size_t)e * DMODEL + d) * RANK];
            const float4* vv = (const float4*)sv[j];
#pragma unroll
            for (int q = 0; q < 4; q++) {
                float4 b4 = db[q], v4 = vv[q];
                acc = fmaf(v4.x, b4.x, acc); acc = fmaf(v4.y, b4.y, acc);
                acc = fmaf(v4.z, b4.z, acc); acc = fmaf(v4.w, b4.w, acc);
            }
        }
        out[(size_t)t * DMODEL + d] = ALPHA * acc;
    }
}

// ---------------- launch -----------------------------------------------------
extern "C" void kernel_launch(void* const* d_in, const int* in_sizes, int n_in,
                              void* d_out, int out_size) {
    const float* x      = (const float*)d_in[0];
    const float* gate_w = (const float*)d_in[1];
    const float* w_up   = (const float*)d_in[2];
    const float* w_gate = (const float*)d_in[3];
    const float* w_down = (const float*)d_in[4];
    const float* up_A   = (const float*)d_in[5];
    const float* up_B   = (const float*)d_in[6];
    const float* gate_A = (const float*)d_in[7];
    const float* gate_B = (const float*)d_in[8];
    const float* down_A = (const float*)d_in[9];
    const float* down_B = (const float*)d_in[10];
    float* out = (float*)d_out;

    static float *p_topv, *p_wf, *p_xa, *p_vp;
    static int *p_topi, *p_list, *p_off;
    static __half *p_x_hi, *p_wup_hi, *p_wgate_hi, *p_wdown_hi,
                  *p_base_up_h, *p_base_gate_h, *p_mix_hi, *p_waall, *p_dAall, *p_chh;
    static bool inited = false;
    if (!inited) {
        cudaGetSymbolAddress((void**)&p_topv, g_topv);
        cudaGetSymbolAddress((void**)&p_topi, g_topi);
        cudaGetSymbolAddress((void**)&p_wf, g_wf);
        cudaGetSymbolAddress((void**)&p_list, g_list);
        cudaGetSymbolAddress((void**)&p_off, g_off);
        cudaGetSymbolAddress((void**)&p_xa, g_xa_part);
        cudaGetSymbolAddress((void**)&p_vp, g_vpart);
        cudaGetSymbolAddress((void**)&p_x_hi, g_x_hi);
        cudaGetSymbolAddress((void**)&p_wup_hi, g_wup_hi);
        cudaGetSymbolAddress((void**)&p_wgate_hi, g_wgate_hi);
        cudaGetSymbolAddress((void**)&p_wdown_hi, g_wdown_hi);
        cudaGetSymbolAddress((void**)&p_base_up_h, g_base_up_h);
        cudaGetSymbolAddress((void**)&p_base_gate_h, g_base_gate_h);
        cudaGetSymbolAddress((void**)&p_mix_hi, g_mix_hi);
        cudaGetSymbolAddress((void**)&p_waall, g_waall_hi);
        cudaGetSymbolAddress((void**)&p_dAall, g_dAall_hi);
        cudaGetSymbolAddress((void**)&p_chh, g_ch_h);
        cudaFuncSetAttribute((const void*)gemm_mma<false, false>,
                             cudaFuncAttributeMaxDynamicSharedMemorySize, GEMM_DSMEM);
        cudaFuncSetAttribute((const void*)gemm_mma<true, false>,
                             cudaFuncAttributeMaxDynamicSharedMemorySize, GEMM_DSMEM);
        cudaFuncSetAttribute((const void*)gemm_mma<false, true>,
                             cudaFuncAttributeMaxDynamicSharedMemorySize, GEMM_DSMEM);
        inited = true;
    }

    // #0: w_up conversion    #1: x conversion    #2: router
    {
        long long n8 = (long long)HID * DMODEL / 8;
        cvt1_kernel<<<(unsigned)((n8 + 255) / 256), 256>>>(w_up, p_wup_hi, n8);
        n8 = (long long)TOK * DMODEL / 8;
        cvt1_kernel<<<(unsigned)((n8 + 255) / 256), 256>>>(x, p_x_hi, n8);
    }
    router_kernel<<<TOK / 8, 256>>>(x, gate_w, p_topv, p_topi);
    // #3: up projection GEMM (fp16 out)  <-- ncu -s 5 target (2 hidden launches)
    {
        dim3 grid(HID / TN, TOK / TM, 1);
        gemm_mma<false, true><<<grid, 256, GEMM_DSMEM>>>(p_x_hi, p_wup_hi,
                                                         p_base_up_h, TOK, HID, DMODEL);
    }
    // #4: w_gate conversion, #5: gate GEMM (fp16 out)
    {
        long long n8 = (long long)HID * DMODEL / 8;
        cvt1_kernel<<<(unsigned)((n8 + 255) / 256), 256>>>(w_gate, p_wgate_hi, n8);
        dim3 grid(HID / TN, TOK / TM, 1);
        gemm_mma<false, true><<<grid, 256, GEMM_DSMEM>>>(p_x_hi, p_wgate_hi,
                                                         p_base_gate_h, TOK, HID, DMODEL);
    }
    // #6-#9: remaining conversions
    {
        long long n8 = (long long)DMODEL * HID / 8;
        cvt1_kernel<<<(unsigned)((n8 + 255) / 256), 256>>>(w_down, p_wdown_hi, n8);
        n8 = (long long)128 * DMODEL / 8;
        cvt1_kernel<<<(unsigned)((n8 + 255) / 256), 256>>>(up_A, p_waall, n8);
        cvt1_kernel<<<(unsigned)((n8 + 255) / 256), 256>>>(gate_A, p_waall + 128 * DMODEL, n8);
        n8 = (long long)128 * HID / 8;
        cvt1_kernel<<<(unsigned)((n8 + 255) / 256), 256>>>(down_A, p_dAall, n8);
    }
    // #10-#11: routing finish
    route_compact_kernel<<<1, 256>>>(p_topi, p_list, p_off);
    seq_softmax_kernel<<<4, SEQ>>>(p_topv, p_wf);
    // #12: xa_all = x @ [upA_all; gateA_all]^T  (K-split x4)
    {
        dim3 grid(256 / TN, TOK / TM, 4);
        gemm_mma<false, false><<<grid, 256, GEMM_DSMEM>>>(p_x_hi, p_waall,
                                                          p_xa, TOK, 256, DMODEL);
    }
    // #13: expert-grouped routed hidden -> fp16 ch (stacked)
    moe_hidden_kernel<<<256, 256>>>(up_B, gate_B);
    // #14: combine -> mix fp16
    {
        long long n8 = (long long)TOK * HID / 8;
        combine_kernel<<<(unsigned)((n8 + 255) / 256), 256>>>(n8);
    }
    // #15: v = [ch0; ch1] @ downA_all^T  (stacked M=4096, K-split x4)
    {
        dim3 grid(128 / TN, 2 * TOK / TM, 4);
        gemm_mma<false, false><<<grid, 256, GEMM_DSMEM>>>(p_chh, p_dAall,
                                                          p_vp, 2 * TOK, 128, HID);
    }
    // #16: lora_down -> out
    lora_down_kernel<<<TOK, 256>>>(down_B, out);
    // #17: out += mixed @ w_down^T
    {
        dim3 grid(DMODEL / TN, TOK / TM, 1);
        gemm_mma<true, false><<<grid, 256, GEMM_DSMEM>>>(p_mix_hi, p_wdown_hi,
                                                         out, TOK, DMODEL, HID);
    }
}

// round 17
// speedup vs baseline: 4.3580x; 1.0753x over previous
#include <cuda_runtime.h>
#include <cuda_fp16.h>
#include <math_constants.h>
#include <cstdint>

// Problem dims (fixed by the dataset)
#define TOK    2048      // B*S = 2*1024
#define DMODEL 2048
#define HID    5632
#define NEXP   8
#define RANK   16
#define SEQ    1024
#define ALPHA  2.0f

#define NUG    11520     // 5632 up | 5632 gate | 128 upA | 128 gateA
#define XA_UP_OFF   11264
#define XA_GATE_OFF 11392

// ---------------- scratch (static __device__ — no allocation allowed) -------
__device__ __align__(256) float g_topv[TOK * 2];
__device__ __align__(256) int   g_topi[TOK * 2];
__device__ __align__(256) float g_wf[TOK * 2];
__device__ __align__(256) int   g_list[TOK * 2];
__device__ __align__(256) int   g_off[NEXP + 1];
__device__ __align__(256) float g_vpart[4 * 2 * TOK * 128];    // K-split v GEMM out

// fp16 operands / intermediates
__device__ __align__(256) __half g_x_hi[(size_t)TOK * DMODEL];
__device__ __align__(256) __half g_wB[(size_t)NUG * DMODEL];   // stacked B
__device__ __align__(256) __half g_wdown_hi[(size_t)DMODEL * HID];
__device__ __align__(256) __half g_ug_h[(size_t)TOK * NUG];    // merged GEMM out
__device__ __align__(256) __half g_mix_hi[(size_t)TOK * HID];
__device__ __align__(256) __half g_dAall_hi[128 * HID];        // downA_all
__device__ __align__(256) __half g_ch_h[(size_t)2 * TOK * HID];// stacked fp16 ch

// ---------------- helpers ----------------------------------------------------
__device__ __forceinline__ uint32_t smem_u32(const void* p) {
    uint32_t a;
    asm("{ .reg .u64 t; cvta.to.shared.u64 t, %1; cvt.u32.u64 %0, t; }"
        : "=r"(a) : "l"(p));
    return a;
}
__device__ __forceinline__ void cp16(uint32_t saddr, const void* gaddr) {
    asm volatile("cp.async.cg.shared.global [%0], [%1], 16;"
                 :: "r"(saddr), "l"(gaddr) : "memory");
}
__device__ __forceinline__ void cp_commit() {
    asm volatile("cp.async.commit_group;" ::: "memory");
}
template <int N>
__device__ __forceinline__ void cp_wait() {
    asm volatile("cp.async.wait_group %0;" :: "n"(N) : "memory");
}
__device__ __forceinline__ void ldsm_x4(uint32_t& r0, uint32_t& r1, uint32_t& r2,
                                        uint32_t& r3, uint32_t addr) {
    asm volatile("ldmatrix.sync.aligned.m8n8.x4.shared.b16 {%0,%1,%2,%3}, [%4];"
                 : "=r"(r0), "=r"(r1), "=r"(r2), "=r"(r3) : "r"(addr));
}
__device__ __forceinline__ void mma_f16(float* c, const uint32_t* a, const uint32_t* b) {
    asm volatile(
        "mma.sync.aligned.m16n8k16.row.col.f32.f16.f16.f32 "
        "{%0,%1,%2,%3}, {%4,%5,%6,%7}, {%8,%9}, {%0,%1,%2,%3};"
        : "+f"(c[0]), "+f"(c[1]), "+f"(c[2]), "+f"(c[3])
        : "r"(a[0]), "r"(a[1]), "r"(a[2]), "r"(a[3]), "r"(b[0]), "r"(b[1]));
}

// ---------------- router: logits + top-2 -------------------------------------
__global__ void router_kernel(const float* __restrict__ x,
                              const float* __restrict__ gw,
                              float* __restrict__ topv, int* __restrict__ topi) {
    int warp = threadIdx.x >> 5, lane = threadIdx.x & 31;
    int t = blockIdx.x * 8 + warp;
    const float* xr = x + (size_t)t * DMODEL;
    float p[NEXP];
#pragma unroll
    for (int e = 0; e < NEXP; e++) p[e] = 0.f;
    for (int d = lane; d < DMODEL; d += 32) {
        float xv = xr[d];
#pragma unroll
        for (int e = 0; e < NEXP; e++) p[e] = fmaf(xv, gw[e * DMODEL + d], p[e]);
    }
#pragma unroll
    for (int e = 0; e < NEXP; e++)
#pragma unroll
        for (int o = 16; o > 0; o >>= 1) p[e] += __shfl_xor_sync(~0u, p[e], o);
    if (lane == 0) {
        int i0 = 0; float v0 = p[0];
#pragma unroll
        for (int e = 1; e < NEXP; e++) if (p[e] > v0) { v0 = p[e]; i0 = e; }
        int i1 = -1; float v1 = -CUDART_INF_F;
#pragma unroll
        for (int e = 0; e < NEXP; e++) if (e != i0 && p[e] > v1) { v1 = p[e]; i1 = e; }
        topv[t * 2 + 0] = v0; topv[t * 2 + 1] = v1;
        topi[t * 2 + 0] = i0; topi[t * 2 + 1] = i1;
    }
}

// ---------------- softmax over the SEQUENCE axis per (batch, slot) ----------
__global__ void seq_softmax_kernel(const float* __restrict__ topv,
                                   float* __restrict__ wf) {
    int b = blockIdx.x >> 1, j = blockIdx.x & 1;
    int s = threadIdx.x;
    int lane = s & 31, warp = s >> 5;
    __shared__ float red[32];
    __shared__ float bc;
    float v = topv[(size_t)(b * SEQ + s) * 2 + j];
    float m = v;
#pragma unroll
    for (int o = 16; o > 0; o >>= 1) m = fmaxf(m, __shfl_xor_sync(~0u, m, o));
    if (lane == 0) red[warp] = m;
    __syncthreads();
    if (s < 32) {
        float mm = red[s];
#pragma unroll
        for (int o = 16; o > 0; o >>= 1) mm = fmaxf(mm, __shfl_xor_sync(~0u, mm, o));
        if (s == 0) bc = mm;
    }
    __syncthreads();
    float M = bc;
    float ev = __expf(v - M);
    float su = ev;
#pragma unroll
    for (int o = 16; o > 0; o >>= 1) su += __shfl_xor_sync(~0u, su, o);
    __syncthreads();
    if (lane == 0) red[warp] = su;
    __syncthreads();
    if (s < 32) {
        float ss = red[s];
#pragma unroll
        for (int o = 16; o > 0; o >>= 1) ss += __shfl_xor_sync(~0u, ss, o);
        if (s == 0) bc = ss;
    }
    __syncthreads();
    wf[(size_t)(b * SEQ + s) * 2 + j] = ev / bc;
}

// ---------------- route compaction -------------------------------------------
__global__ void route_compact_kernel(const int* __restrict__ topi,
                                     int* __restrict__ list, int* __restrict__ off) {
    __shared__ int scnt[NEXP], scur[NEXP];
    int tid = threadIdx.x;
    if (tid < NEXP) scnt[tid] = 0;
    __syncthreads();
    for (int i = tid; i < TOK * 2; i += 256) atomicAdd(&scnt[topi[i]], 1);
    __syncthreads();
    if (tid == 0) {
        int o = 0;
        for (int e = 0; e < NEXP; e++) { off[e] = o; scur[e] = o; o += scnt[e]; }
        off[NEXP] = o;
    }
    __syncthreads();
    for (int i = tid; i < TOK * 2; i += 256) {
        int p = atomicAdd(&scur[topi[i]], 1);
        list[p] = i;
    }
}

// ---------------- fp32 -> fp16 (single rounding) ----------------------------
__global__ void cvt1_kernel(const float* __restrict__ src,
                            __half* __restrict__ hi, long long n8) {
    long long i = (long long)blockIdx.x * blockDim.x + threadIdx.x;
    if (i >= n8) return;
    const float4* s = (const float4*)src + i * 2;
    float4 a = s[0], b = s[1];
    float v[8] = {a.x, a.y, a.z, a.w, b.x, b.y, b.z, b.w};
    __half h[8];
#pragma unroll
    for (int q = 0; q < 8; q++) h[q] = __float2half(v[q]);
    *((uint4*)hi + i) = *(const uint4*)h;
}

// ---------------- stacked-B conversion: w_up|w_gate|upA|gateA ---------------
__global__ void cvt_wB_kernel(const float* __restrict__ wup,
                              const float* __restrict__ wgate,
                              const float* __restrict__ upA,
                              const float* __restrict__ gateA) {
    const long long N1 = (long long)HID * DMODEL / 8;        // up
    const long long N2 = 2 * N1;                             // +gate
    const long long N3 = N2 + (long long)128 * DMODEL / 8;   // +upA
    const long long N4 = N3 + (long long)128 * DMODEL / 8;   // +gateA
    long long i = (long long)blockIdx.x * blockDim.x + threadIdx.x;
    if (i >= N4) return;
    const float* src;
    long long local;
    if (i < N1)      { src = wup;   local = i; }
    else if (i < N2) { src = wgate; local = i - N1; }
    else if (i < N3) { src = upA;   local = i - N2; }
    else             { src = gateA; local = i - N3; }
    const float4* s = (const float4*)src + local * 2;
    float4 a = s[0], b = s[1];
    float v[8] = {a.x, a.y, a.z, a.w, b.x, b.y, b.z, b.w};
    __half h[8];
#pragma unroll
    for (int q = 0; q < 8; q++) h[q] = __float2half(v[q]);
    *((uint4*)g_wB + i) = *(const uint4*)h;
}

// ---------------- HMMA GEMM  C[M,N] (+)= A[M,K] B[N,K]^T --------------------
// TKC=64, STAGES=3 (110.6 KB smem, 2 CTAs/SM). gridDim.z = K-split slices.
#define TM 128
#define TN 128
#define TKC 64
#define ASTR 72           // 64 data + 8 pad halves; 144B rows, ldsm conflict-free
#define STAGES 3
#define STG_ELEMS (TM * ASTR)
#define GEMM_DSMEM (STAGES * STG_ELEMS * 2 * 2)   // 110592 B

template <bool ADD_C, bool HALF_OUT>
__global__ __launch_bounds__(256, 2)
void gemm_mma(const __half* __restrict__ A,
              const __half* __restrict__ B,
              void* __restrict__ Cv, int M, int N, int K) {
    extern __shared__ __half smem[];
    __half* sA = smem;
    __half* sB = smem + STAGES * STG_ELEMS;

    int tid = threadIdx.x;
    int wid = tid >> 5, lane = tid & 31;
    int wm = (wid >> 1) * 32;
    int wn = (wid & 1) * 64;

    int Ks = K / gridDim.z;
    int kbase = blockIdx.z * Ks;

    int bm = blockIdx.y * TM;
    int bn = blockIdx.x * TN;
    int niter = Ks / TKC;

    uint32_t sA_u = smem_u32(sA);
    uint32_t sB_u = smem_u32(sB);

    int lrow8 = tid >> 3;         // 0..31 base rows (x4 iterations -> 128)
    int lseg = tid & 7;           // 8 x 16B segments per 128B row

    auto load_stage = [&](int it) {
        int s = it % STAGES;
        int k0 = kbase + it * TKC;
        const __half* Asrc = A + (size_t)bm * K + k0;
        const __half* Bsrc = B + (size_t)bn * K + k0;
        uint32_t so = (uint32_t)(s * STG_ELEMS) * 2u;
#pragma unroll
        for (int q = 0; q < 4; q++) {
            int r = lrow8 + q * 32;
            uint32_t off = so + (uint32_t)(r * ASTR + lseg * 8) * 2u;
            cp16(sA_u + off, Asrc + (size_t)r * K + lseg * 8);
            cp16(sB_u + off, Bsrc + (size_t)r * K + lseg * 8);
        }
    };

    float acc[2][8][4];
#pragma unroll
    for (int mt = 0; mt < 2; mt++)
#pragma unroll
        for (int nt = 0; nt < 8; nt++)
#pragma unroll
            for (int q = 0; q < 4; q++) acc[mt][nt][q] = 0.f;

#pragma unroll
    for (int it = 0; it < STAGES - 1; it++) { load_stage(it); cp_commit(); }

    int lm = lane & 15;
    int lk = (lane >> 4) * 8;

    for (int it = 0; it < niter; it++) {
        cp_wait<STAGES - 2>();
        __syncthreads();
        if (it + STAGES - 1 < niter) load_stage(it + STAGES - 1);
        cp_commit();

        int s = it % STAGES;
        uint32_t sAo = sA_u + (uint32_t)(s * STG_ELEMS) * 2u;
        uint32_t sBo = sB_u + (uint32_t)(s * STG_ELEMS) * 2u;
#pragma unroll
        for (int kk = 0; kk < 4; kk++) {       // four k16 slices of the 64-chunk
            uint32_t a[2][4];
#pragma unroll
            for (int mt = 0; mt < 2; mt++) {
                uint32_t addr = sAo +
                    (uint32_t)((wm + mt * 16 + lm) * ASTR + kk * 16 + lk) * 2u;
                ldsm_x4(a[mt][0], a[mt][1], a[mt][2], a[mt][3], addr);
            }
            uint32_t b[8][2];
#pragma unroll
            for (int np = 0; np < 4; np++) {
                uint32_t r0, r1, r2, r3;
                uint32_t addr = sBo +
                    (uint32_t)((wn + np * 16 + lm) * ASTR + kk * 16 + lk) * 2u;
                ldsm_x4(r0, r1, r2, r3, addr);
                b[np * 2 + 0][0] = r0; b[np * 2 + 0][1] = r2;
                b[np * 2 + 1][0] = r1; b[np * 2 + 1][1] = r3;
            }
#pragma unroll
            for (int mt = 0; mt < 2; mt++)
#pragma unroll
                for (int nt = 0; nt < 8; nt++)
                    mma_f16(acc[mt][nt], a[mt], b[nt]);
        }
    }

    int rbase = bm + wm + (lane >> 2);
    int cbase = bn + wn + (lane & 3) * 2;
    if (HALF_OUT) {
        __half* C = (__half*)Cv + (size_t)blockIdx.z * M * N;
#pragma unroll
        for (int mt = 0; mt < 2; mt++) {
#pragma unroll
            for (int nt = 0; nt < 8; nt++) {
                __half* p0 = C + (size_t)(rbase + mt * 16) * N + cbase + nt * 8;
                __half* p1 = p0 + (size_t)8 * N;
                *(__half2*)p0 = __floats2half2_rn(acc[mt][nt][0], acc[mt][nt][1]);
                *(__half2*)p1 = __floats2half2_rn(acc[mt][nt][2], acc[mt][nt][3]);
            }
        }
    } else {
        float* C = (float*)Cv + (size_t)blockIdx.z * M * N;
#pragma unroll
        for (int mt = 0; mt < 2; mt++) {
#pragma unroll
            for (int nt = 0; nt < 8; nt++) {
                float* p0 = C + (size_t)(rbase + mt * 16) * N + cbase + nt * 8;
                float* p1 = p0 + (size_t)8 * N;
                float2 v0 = make_float2(acc[mt][nt][0], acc[mt][nt][1]);
                float2 v1 = make_float2(acc[mt][nt][2], acc[mt][nt][3]);
                if (ADD_C) {
                    float2 o0 = *(const float2*)p0;
                    float2 o1 = *(const float2*)p1;
                    v0.x += o0.x; v0.y += o0.y;
                    v1.x += o1.x; v1.y += o1.y;
                }
                *(float2*)p0 = v0;
                *(float2*)p1 = v1;
            }
        }
    }
}

// ---------------- expert-grouped routed hidden (fp16 ch out) ----------------
__global__ __launch_bounds__(256)
void moe_hidden_kernel(const float* __restrict__ upB,
                       const float* __restrict__ gateB) {
    int e = blockIdx.x & 7;
    int g = blockIdx.x >> 3;
    int tid = threadIdx.x;
    int wid = tid >> 5, lane = tid & 31;

    __shared__ int st[16], sslot[16];
    __shared__ float sc[16];
    __shared__ __align__(16) float sxu[16][16];
    __shared__ __align__(16) float sxg[16][16];

    int o0 = g_off[e], cnt = g_off[e + 1] - o0;

    for (int base = g * 16; base < cnt; base += 32 * 16) {
        int nb = min(16, cnt - base);
        __syncthreads();
        if (tid < 16) {
            if (tid < nb) {
                int a = g_list[o0 + base + tid];
                st[tid] = a >> 1; sslot[tid] = a & 1; sc[tid] = g_wf[a];
            } else { st[tid] = 0; sslot[tid] = 0; sc[tid] = 0.f; }
        }
        __syncthreads();
        {
            int j = tid >> 4, r = tid & 15;
            int t = st[j];
            sxu[j][r] = __half2float(g_ug_h[(size_t)t * NUG + XA_UP_OFF + e * 16 + r]);
            sxg[j][r] = __half2float(g_ug_h[(size_t)t * NUG + XA_GATE_OFF + e * 16 + r]);
        }
        __syncthreads();

        for (int hb = 0; hb < HID; hb += 256) {
            int h = hb + wid * 32 + lane;
            float ub[16], gb[16];
            const float4* up4 = (const float4*)&upB[((size_t)e * HID + h) * RANK];
            const float4* gb4 = (const float4*)&gateB[((size_t)e * HID + h) * RANK];
#pragma unroll
            for (int q = 0; q < 4; q++) {
                float4 u = up4[q]; ub[q*4+0]=u.x; ub[q*4+1]=u.y; ub[q*4+2]=u.z; ub[q*4+3]=u.w;
                float4 gg = gb4[q]; gb[q*4+0]=gg.x; gb[q*4+1]=gg.y; gb[q*4+2]=gg.z; gb[q*4+3]=gg.w;
            }
            for (int j = 0; j < nb; j++) {
                int t = st[j];
                float bu = __half2float(g_ug_h[(size_t)t * NUG + h]);
                float bg = __half2float(g_ug_h[(size_t)t * NUG + HID + h]);
                float lu = 0.f, lg = 0.f;
#pragma unroll
                for (int r = 0; r < 16; r++) {
                    lu = fmaf(sxu[j][r], ub[r], lu);
                    lg = fmaf(sxg[j][r], gb[r], lg);
                }
                float uu = bu + ALPHA * lu;
                float gg = bg + ALPHA * lg;
                float ch = sc[j] * (uu / (1.f + __expf(-uu))) * gg;
                g_ch_h[((size_t)sslot[j] * TOK + t) * HID + h] = __float2half(ch);
            }
        }
    }
}

// ---------------- combine: mix = ch0+ch1 (fp16 in, fp16 out) ----------------
__global__ void combine_kernel(long long n8) {
    long long i = (long long)blockIdx.x * blockDim.x + threadIdx.x;
    if (i >= n8) return;
    uint4 u0 = *((const uint4*)g_ch_h + i);
    uint4 u1 = *((const uint4*)(g_ch_h + (size_t)TOK * HID) + i);
    const __half2* a = (const __half2*)&u0;
    const __half2* b = (const __half2*)&u1;
    uint4 o;
    __half2* ov = (__half2*)&o;
#pragma unroll
    for (int q = 0; q < 4; q++) {
        float2 fa = __half22float2(a[q]);
        float2 fb = __half22float2(b[q]);
        ov[q] = __floats2half2_rn(fa.x + fb.x, fa.y + fb.y);
    }
    *((uint4*)g_mix_hi + i) = o;
}

// ---------------- lora_down: out = ALPHA * (v_sel @ downB_sel^T) -------------
__global__ void lora_down_kernel(const float* __restrict__ downB,
                                 float* __restrict__ out) {
    int t = blockIdx.x;
    int tid = threadIdx.x;
    __shared__ __align__(16) float sv[2][16];
    __shared__ int se[2];
    if (tid < 2) se[tid] = g_topi[t * 2 + tid];
    __syncthreads();
    if (tid < 32) {
        int j = tid >> 4, r = tid & 15;
        int e = se[j];
        float s = 0.f;
#pragma unroll
        for (int z = 0; z < 4; z++)
            s += g_vpart[((size_t)z * 2 * TOK + (size_t)j * TOK + t) * 128 + e * 16 + r];
        sv[j][r] = s;
    }
    __syncthreads();
    int e0 = se[0], e1 = se[1];
    for (int d = tid; d < DMODEL; d += 256) {
        float acc = 0.f;
#pragma unroll
        for (int j = 0; j < 2; j++) {
            int e = j ? e1 : e0;
            const float4* db = (const float4*)&downB[((size_t)e * DMODEL + d) * RANK];
            const float4* vv = (const float4*)sv[j];
#pragma unroll
            for (int q = 0; q < 4; q++) {
                float4 b4 = db[q], v4 = vv[q];
                acc = fmaf(v4.x, b4.x, acc); acc = fmaf(v4.y, b4.y, acc);
                acc = fmaf(v4.z, b4.z, acc); acc = fmaf(v4.w, b4.w, acc);
            }
        }
        out[(size_t)t * DMODEL + d] = ALPHA * acc;
    }
}

// ---------------- launch -----------------------------------------------------
extern "C" void kernel_launch(void* const* d_in, const int* in_sizes, int n_in,
                              void* d_out, int out_size) {
    const float* x      = (const float*)d_in[0];
    const float* gate_w = (const float*)d_in[1];
    const float* w_up   = (const float*)d_in[2];
    const float* w_gate = (const float*)d_in[3];
    const float* w_down = (const float*)d_in[4];
    const float* up_A   = (const float*)d_in[5];
    const float* up_B   = (const float*)d_in[6];
    const float* gate_A = (const float*)d_in[7];
    const float* gate_B = (const float*)d_in[8];
    const float* down_A = (const float*)d_in[9];
    const float* down_B = (const float*)d_in[10];
    float* out = (float*)d_out;

    static float *p_topv, *p_wf, *p_vp;
    static int *p_topi, *p_list, *p_off;
    static __half *p_x_hi, *p_wB, *p_wdown_hi, *p_ug, *p_mix_hi, *p_dAall, *p_chh;
    static bool inited = false;
    if (!inited) {
        cudaGetSymbolAddress((void**)&p_topv, g_topv);
        cudaGetSymbolAddress((void**)&p_topi, g_topi);
        cudaGetSymbolAddress((void**)&p_wf, g_wf);
        cudaGetSymbolAddress((void**)&p_list, g_list);
        cudaGetSymbolAddress((void**)&p_off, g_off);
        cudaGetSymbolAddress((void**)&p_vp, g_vpart);
        cudaGetSymbolAddress((void**)&p_x_hi, g_x_hi);
        cudaGetSymbolAddress((void**)&p_wB, g_wB);
        cudaGetSymbolAddress((void**)&p_wdown_hi, g_wdown_hi);
        cudaGetSymbolAddress((void**)&p_ug, g_ug_h);
        cudaGetSymbolAddress((void**)&p_mix_hi, g_mix_hi);
        cudaGetSymbolAddress((void**)&p_dAall, g_dAall_hi);
        cudaGetSymbolAddress((void**)&p_chh, g_ch_h);
        cudaFuncSetAttribute((const void*)gemm_mma<false, false>,
                             cudaFuncAttributeMaxDynamicSharedMemorySize, GEMM_DSMEM);
        cudaFuncSetAttribute((const void*)gemm_mma<true, false>,
                             cudaFuncAttributeMaxDynamicSharedMemorySize, GEMM_DSMEM);
        cudaFuncSetAttribute((const void*)gemm_mma<false, true>,
                             cudaFuncAttributeMaxDynamicSharedMemorySize, GEMM_DSMEM);
        inited = true;
    }

    // #0: stacked-B conversion (w_up | w_gate | upA | gateA)
    {
        long long n8 = (long long)NUG * DMODEL / 8;
        cvt_wB_kernel<<<(unsigned)((n8 + 255) / 256), 256>>>(w_up, w_gate, up_A, gate_A);
    }
    // #1: x conversion, #2: router
    {
        long long n8 = (long long)TOK * DMODEL / 8;
        cvt1_kernel<<<(unsigned)((n8 + 255) / 256), 256>>>(x, p_x_hi, n8);
    }
    router_kernel<<<TOK / 8, 256>>>(x, gate_w, p_topv, p_topi);
    // #3: merged up|gate|xa GEMM (fp16 out)  <-- ncu -s 5 lands here
    {
        dim3 grid(NUG / TN, TOK / TM, 1);
        gemm_mma<false, true><<<grid, 256, GEMM_DSMEM>>>(p_x_hi, p_wB,
                                                         p_ug, TOK, NUG, DMODEL);
    }
    // #4-#5: remaining conversions
    {
        long long n8 = (long long)DMODEL * HID / 8;
        cvt1_kernel<<<(unsigned)((n8 + 255) / 256), 256>>>(w_down, p_wdown_hi, n8);
        n8 = (long long)128 * HID / 8;
        cvt1_kernel<<<(unsigned)((n8 + 255) / 256), 256>>>(down_A, p_dAall, n8);
    }
    // #6-#7: routing finish
    route_compact_kernel<<<1, 256>>>(p_topi, p_list, p_off);
    seq_softmax_kernel<<<4, SEQ>>>(p_topv, p_wf);
    // #8: expert-grouped routed hidden -> fp16 ch (stacked)
    moe_hidden_kernel<<<256, 256>>>(up_B, gate_B);
    // #9: combine -> mix fp16
    {
        long long n8 = (long long)TOK * HID / 8;
        combine_kernel<<<(unsigned)((n8 + 255) / 256), 256>>>(n8);
    }
    // #10: v = [ch0; ch1] @ downA_all^T  (stacked M=4096, K-split x4)
    {
        dim3 grid(128 / TN, 2 * TOK / TM, 4);
        gemm_mma<false, false><<<grid, 256, GEMM_DSMEM>>>(p_chh, p_dAall,
                                                          p_vp, 2 * TOK, 128, HID);
    }
    // #11: lora_down -> out
    lora_down_kernel<<<TOK, 256>>>(down_B, out);
    // #12: out += mixed @ w_down^T
    {
        dim3 grid(DMODEL / TN, TOK / TM, 1);
        gemm_mma<true, false><<<grid, 256, GEMM_DSMEM>>>(p_mix_hi, p_wdown_hi,
                                                         out, TOK, DMODEL, HID);
    }
}